// round 1
// baseline (speedup 1.0000x reference)
#include <cuda_runtime.h>
#include <math.h>

#define BB 2
#define SS 2048
#define DD 1024
#define HH 16
#define HD 64
#define BH (BB*HH)
#define NKEEP 675
#define W2 64
#define ROWT 16
#define COLT 128

// ---------------- scratch (device globals; no allocation allowed) -------------
__device__ float g_q[BB*HH*SS*HD];
__device__ float g_k[BB*HH*SS*HD];
__device__ float g_v[BB*HH*SS*HD];
__device__ float g_o[BB*HH*SS*HD];
__device__ float g_sq[BH*SS];
__device__ float g_d2c[BH*SS];
__device__ float g_d2cmax[BH];
__device__ float g_kd[BH*SS];
__device__ float g_kdmax[BH];
__device__ float g_tls[BH*SS];
__device__ int   g_mark[BH*SS];

// ---------------- K1: QKV GEMM: (4096x1024) @ (3072x1024)^T + b --------------
__global__ __launch_bounds__(256) void qkv_gemm(const float* __restrict__ x,
                                                const float* __restrict__ w,
                                                const float* __restrict__ bias) {
    __shared__ float As[64][17];
    __shared__ float Ws[64][17];
    int bm = blockIdx.y, bn = blockIdx.x;
    int t = threadIdx.x;
    int tx = t & 15, ty = t >> 4;
    float acc[4][4] = {};
    const int K = DD;
    for (int k0 = 0; k0 < K; k0 += 16) {
        for (int idx = t; idx < 64 * 16; idx += 256) {
            int r = idx >> 4, c = idx & 15;
            As[r][c] = x[(size_t)(bm * 64 + r) * K + k0 + c];
            Ws[r][c] = w[(size_t)(bn * 64 + r) * K + k0 + c];
        }
        __syncthreads();
#pragma unroll
        for (int kk = 0; kk < 16; ++kk) {
            float a[4], bv[4];
#pragma unroll
            for (int i = 0; i < 4; i++) a[i] = As[ty + i * 16][kk];
#pragma unroll
            for (int j = 0; j < 4; j++) bv[j] = Ws[tx + j * 16][kk];
#pragma unroll
            for (int i = 0; i < 4; i++)
#pragma unroll
                for (int j = 0; j < 4; j++) acc[i][j] += a[i] * bv[j];
        }
        __syncthreads();
    }
#pragma unroll
    for (int i = 0; i < 4; i++) {
        int gr = bm * 64 + ty + i * 16;
        int b = gr >> 11;
        int s = gr & (SS - 1);
#pragma unroll
        for (int j = 0; j < 4; j++) {
            int gc = bn * 64 + tx + j * 16;
            float v = acc[i][j] + bias[gc];
            int which = gc >> 10;
            int hh = (gc >> 6) & 15;
            int dd = gc & 63;
            float* dst = (which == 0) ? g_q : (which == 1) ? g_k : g_v;
            dst[((size_t)((b * HH + hh) * SS + s)) * HD + dd] = v;
        }
    }
}

// ---------------- K2: per-head centroid, sq norms, d2c, d2c max --------------
__global__ __launch_bounds__(256) void stats_kernel(const float* __restrict__ x) {
    int bh = blockIdx.x;
    int b = bh / HH, h = bh % HH;
    int t = threadIdx.x;
    __shared__ float part[256];
    __shared__ float cent[64];
    int d = t & 63, grp = t >> 6;
    float acc = 0.f;
    for (int s = grp; s < SS; s += 4)
        acc += x[((size_t)(b * SS + s)) * DD + h * HD + d];
    part[t] = acc;
    __syncthreads();
    if (t < 64) cent[t] = (part[t] + part[t + 64] + part[t + 128] + part[t + 192]) * (1.0f / SS);
    __syncthreads();
    float lmax = 0.f;
    for (int s = t; s < SS; s += 256) {
        const float* xp = x + (size_t)(b * SS + s) * DD + h * HD;
        float sq = 0.f, dc2 = 0.f;
#pragma unroll
        for (int dd = 0; dd < HD; ++dd) {
            float v = xp[dd];
            sq += v * v;
            float wv = v - cent[dd];
            dc2 += wv * wv;
        }
        g_sq[bh * SS + s] = sq;
        float dc = sqrtf(dc2);
        g_d2c[bh * SS + s] = dc;
        lmax = fmaxf(lmax, dc);
    }
    __syncthreads();
    part[t] = lmax;
    __syncthreads();
    for (int off = 128; off > 0; off >>= 1) {
        if (t < off) part[t] = fmaxf(part[t], part[t + off]);
        __syncthreads();
    }
    if (t == 0) {
        g_d2cmax[bh] = part[0];
        g_kdmax[bh] = 0.f;
    }
}

// ---------------- K3: pairwise dist^2 GEMM into scratch (attn region) -------
__global__ __launch_bounds__(256) void dist_gemm(const float* __restrict__ x,
                                                 float* __restrict__ dist2) {
    int bh = blockIdx.z;
    int b = bh >> 4, h = bh & 15;
    __shared__ float As[64][17];
    __shared__ float Bs[64][17];
    int bm = blockIdx.y, bn = blockIdx.x;
    int t = threadIdx.x;
    int tx = t & 15, ty = t >> 4;
    float acc[4][4] = {};
    const float* base = x + (size_t)b * SS * DD + h * HD;
    for (int k0 = 0; k0 < HD; k0 += 16) {
        for (int idx = t; idx < 64 * 16; idx += 256) {
            int r = idx >> 4, c = idx & 15;
            As[r][c] = base[(size_t)(bm * 64 + r) * DD + k0 + c];
            Bs[r][c] = base[(size_t)(bn * 64 + r) * DD + k0 + c];
        }
        __syncthreads();
#pragma unroll
        for (int kk = 0; kk < 16; ++kk) {
            float a[4], bv[4];
#pragma unroll
            for (int i = 0; i < 4; i++) a[i] = As[ty + i * 16][kk];
#pragma unroll
            for (int j = 0; j < 4; j++) bv[j] = Bs[tx + j * 16][kk];
#pragma unroll
            for (int i = 0; i < 4; i++)
#pragma unroll
                for (int j = 0; j < 4; j++) acc[i][j] += a[i] * bv[j];
        }
        __syncthreads();
    }
#pragma unroll
    for (int i = 0; i < 4; i++) {
        int gi = bm * 64 + ty + i * 16;
        float sqi = g_sq[bh * SS + gi];
#pragma unroll
        for (int j = 0; j < 4; j++) {
            int gj = bn * 64 + tx + j * 16;
            float d2 = fmaxf(sqi + g_sq[bh * SS + gj] - 2.f * acc[i][j], 0.f);
            dist2[((size_t)bh * SS + gi) * SS + gj] = d2;
        }
    }
}

// ---------------- K4: 10th-smallest distance per row -------------------------
__global__ __launch_bounds__(256) void kth_kernel(const float* __restrict__ dist2) {
    __shared__ float row[SS];
    __shared__ float rv[256];
    __shared__ int ri[256];
    int t = threadIdx.x;
    int s = blockIdx.x;
    int bh = blockIdx.y;
    const float* src = dist2 + ((size_t)bh * SS + s) * SS;
    for (int j = t; j < SS; j += 256) row[j] = src[j];
    __syncthreads();
    float kth = 0.f;
    for (int it = 0; it < 10; ++it) {
        float lv = 1e30f;
        int li = 0;
        for (int j = t; j < SS; j += 256) {
            float v = row[j];
            if (v < lv) { lv = v; li = j; }
        }
        rv[t] = lv;
        ri[t] = li;
        __syncthreads();
        for (int off = 128; off > 0; off >>= 1) {
            if (t < off) {
                if (rv[t + off] < rv[t]) { rv[t] = rv[t + off]; ri[t] = ri[t + off]; }
            }
            __syncthreads();
        }
        kth = rv[0];
        if (t == 0) row[ri[0]] = 1e30f;
        __syncthreads();
    }
    if (t == 0) {
        float kd = sqrtf(kth);
        g_kd[bh * SS + s] = kd;
        atomicMax((int*)&g_kdmax[bh], __float_as_int(kd));
    }
}

// ---------------- K5: tls score ----------------------------------------------
__global__ __launch_bounds__(256) void tls_kernel() {
    int bh = blockIdx.x;
    int t = threadIdx.x;
    float dinv = 1.0f / (g_d2cmax[bh] + 1e-8f);
    float kinv = 1.0f / (g_kdmax[bh] + 1e-8f);
    for (int s = t; s < SS; s += 256) {
        float life = g_d2c[bh * SS + s] * dinv;
        float mmd = g_kd[bh * SS + s] * kinv;
        g_tls[bh * SS + s] = 0.7f * life + 0.3f * mmd;
    }
}

// ---------------- K6: bitonic sort tls per (b,h), mark landmarks -------------
__global__ __launch_bounds__(1024) void sort_mark_kernel() {
    __shared__ float a[SS];
    int t = threadIdx.x;
    int bh = blockIdx.x;
    a[t] = g_tls[bh * SS + t];
    a[t + 1024] = g_tls[bh * SS + t + 1024];
    __syncthreads();
    for (int k = 2; k <= SS; k <<= 1) {
        for (int j = k >> 1; j > 0; j >>= 1) {
#pragma unroll
            for (int half = 0; half < 2; ++half) {
                int i = t + half * 1024;
                int ixj = i ^ j;
                if (ixj > i) {
                    bool up = ((i & k) == 0);
                    float xi = a[i], xj = a[ixj];
                    if (up ? (xi > xj) : (xi < xj)) { a[i] = xj; a[ixj] = xi; }
                }
            }
            __syncthreads();
        }
    }
    float thresh = a[SS - NKEEP];
    __syncthreads();
#pragma unroll
    for (int half = 0; half < 2; ++half) {
        int s = t + half * 1024;
        g_mark[bh * SS + s] = (g_tls[bh * SS + s] >= thresh) ? 1 : 0;
    }
}

// ---------------- K7: fused scores + masked softmax + attn write + AV --------
__global__ __launch_bounds__(256) void attn_kernel(float* __restrict__ attnout) {
    extern __shared__ float smem[];
    float* sc = smem;                       // ROWT * SS
    float* kt = sc + ROWT * SS;             // COLT * 65
    float* qs = kt + COLT * 65;             // ROWT * 65
    int* mk = (int*)(qs + ROWT * 65);       // SS ints

    int bh = blockIdx.y;
    int i0 = blockIdx.x * ROWT;
    int t = threadIdx.x;

    for (int idx = t; idx < ROWT * HD; idx += 256) {
        int r = idx >> 6, d = idx & 63;
        qs[r * 65 + d] = g_q[((size_t)bh * SS + i0 + r) * HD + d];
    }
    for (int j = t; j < SS; j += 256) mk[j] = g_mark[bh * SS + j];
    __syncthreads();

    const float scale = 0.125f;  // 1/sqrt(64)
    int r = t >> 4;
    int cbase = t & 15;

    for (int ct = 0; ct < SS / COLT; ++ct) {
        for (int idx = t; idx < COLT * HD; idx += 256) {
            int c = idx >> 6, d = idx & 63;
            kt[c * 65 + d] = g_k[((size_t)bh * SS + ct * COLT + c) * HD + d];
        }
        __syncthreads();
#pragma unroll
        for (int p = 0; p < 8; p++) {
            int c = cbase + p * 16;
            float dot = 0.f;
#pragma unroll
            for (int d = 0; d < HD; d++) dot += qs[r * 65 + d] * kt[c * 65 + d];
            sc[r * SS + ct * COLT + c] = dot * scale;
        }
        __syncthreads();
    }

    // softmax: 8 warps handle 2 rows each
    int w = t >> 5, lane = t & 31;
    for (int rr = w * 2; rr < w * 2 + 2; ++rr) {
        int i = i0 + rr;
        float m = -1e30f;
        for (int j = lane; j < SS; j += 32) {
            int rel = j - i;
            bool msk = (rel >= -W2 && rel <= W2) || mk[j];
            if (msk) m = fmaxf(m, sc[rr * SS + j]);
        }
        for (int off = 16; off > 0; off >>= 1)
            m = fmaxf(m, __shfl_xor_sync(0xffffffffu, m, off));
        float sum = 0.f;
        for (int j = lane; j < SS; j += 32) {
            int rel = j - i;
            bool msk = (rel >= -W2 && rel <= W2) || mk[j];
            if (msk) sum += __expf(sc[rr * SS + j] - m);
        }
        for (int off = 16; off > 0; off >>= 1)
            sum += __shfl_xor_sync(0xffffffffu, sum, off);
        float inv = 1.0f / sum;
        float* orow = attnout + ((size_t)bh * SS + i) * SS;
        for (int j = lane; j < SS; j += 32) {
            int rel = j - i;
            bool msk = (rel >= -W2 && rel <= W2) || mk[j];
            float v = msk ? __expf(sc[rr * SS + j] - m) * inv : 0.f;
            orow[j] = v;
            sc[rr * SS + j] = v;
        }
    }
    __syncthreads();

    // AV: each thread owns (row r, 4 d-columns)
    int d4 = (t & 15) * 4;
    float acc[4] = {0.f, 0.f, 0.f, 0.f};
    for (int ct = 0; ct < SS / COLT; ++ct) {
        for (int idx = t; idx < COLT * HD; idx += 256) {
            int c = idx >> 6, d = idx & 63;
            kt[c * 65 + d] = g_v[((size_t)bh * SS + ct * COLT + c) * HD + d];
        }
        __syncthreads();
        for (int c = 0; c < COLT; c++) {
            float av = sc[r * SS + ct * COLT + c];
#pragma unroll
            for (int q = 0; q < 4; q++) acc[q] += av * kt[c * 65 + d4 + q];
        }
        __syncthreads();
    }
#pragma unroll
    for (int q = 0; q < 4; q++)
        g_o[((size_t)bh * SS + i0 + r) * HD + d4 + q] = acc[q];
}

// ---------------- K8: output projection (4096x1024) @ (1024x1024)^T + b ------
__global__ __launch_bounds__(256) void proj_gemm(const float* __restrict__ w,
                                                 const float* __restrict__ bias,
                                                 float* __restrict__ out) {
    __shared__ float As[64][17];
    __shared__ float Ws[64][17];
    int bm = blockIdx.y, bn = blockIdx.x;
    int t = threadIdx.x;
    int tx = t & 15, ty = t >> 4;
    float acc[4][4] = {};
    for (int k0 = 0; k0 < DD; k0 += 16) {
        for (int idx = t; idx < 64 * 16; idx += 256) {
            int r = idx >> 4, c = idx & 15;
            int m = bm * 64 + r;
            int k = k0 + c;
            int b = m >> 11;
            int s = m & (SS - 1);
            int h = k >> 6;
            int d = k & 63;
            As[r][c] = g_o[((size_t)((b * HH + h) * SS + s)) * HD + d];
            Ws[r][c] = w[(size_t)(bn * 64 + r) * DD + k0 + c];
        }
        __syncthreads();
#pragma unroll
        for (int kk = 0; kk < 16; ++kk) {
            float a[4], bv[4];
#pragma unroll
            for (int i = 0; i < 4; i++) a[i] = As[ty + i * 16][kk];
#pragma unroll
            for (int j = 0; j < 4; j++) bv[j] = Ws[tx + j * 16][kk];
#pragma unroll
            for (int i = 0; i < 4; i++)
#pragma unroll
                for (int j = 0; j < 4; j++) acc[i][j] += a[i] * bv[j];
        }
        __syncthreads();
    }
#pragma unroll
    for (int i = 0; i < 4; i++) {
        int gr = bm * 64 + ty + i * 16;
#pragma unroll
        for (int j = 0; j < 4; j++) {
            int gc = bn * 64 + tx + j * 16;
            out[(size_t)gr * DD + gc] = acc[i][j] + bias[gc];
        }
    }
}

// ---------------- launch ------------------------------------------------------
extern "C" void kernel_launch(void* const* d_in, const int* in_sizes, int n_in,
                              void* d_out, int out_size) {
    const float* x = (const float*)d_in[0];
    const float* qkv_w = (const float*)d_in[1];
    const float* qkv_b = (const float*)d_in[2];
    const float* out_w = (const float*)d_in[3];
    const float* out_b = (const float*)d_in[4];
    float* out = (float*)d_out;
    float* attn = out + (size_t)BB * SS * DD;  // attn region; also dist2 scratch

    const int SMEM_BYTES = (ROWT * SS + COLT * 65 + ROWT * 65 + SS) * 4;
    cudaFuncSetAttribute(attn_kernel, cudaFuncAttributeMaxDynamicSharedMemorySize,
                         SMEM_BYTES);

    qkv_gemm<<<dim3(3 * DD / 64, BB * SS / 64), 256>>>(x, qkv_w, qkv_b);
    stats_kernel<<<BH, 256>>>(x);
    dist_gemm<<<dim3(SS / 64, SS / 64, BH), 256>>>(x, attn);
    kth_kernel<<<dim3(SS, BH), 256>>>(attn);
    tls_kernel<<<BH, 256>>>();
    sort_mark_kernel<<<BH, 1024>>>();
    attn_kernel<<<dim3(SS / ROWT, BH), 256, SMEM_BYTES>>>(attn);
    proj_gemm<<<dim3(DD / 64, BB * SS / 64), 256>>>(out_w, out_b, out);
}

// round 3
// speedup vs baseline: 3.0415x; 3.0415x over previous
#include <cuda_runtime.h>
#include <math.h>

#define BB 2
#define SS 2048
#define DD 1024
#define HH 16
#define HD 64
#define BH (BB*HH)
#define NKEEP 675
#define W2 64

// ---------------- scratch (device globals) -----------------------------------
__device__ float g_q[BH*SS*HD];
__device__ float g_k[BH*SS*HD];
__device__ float g_v[BH*SS*HD];
__device__ float g_o[BB*SS*DD];     // (B,S,H*D) row-major for proj
__device__ float g_sq[BH*SS];
__device__ float g_d2c[BH*SS];
__device__ float g_d2cmax[BH];
__device__ float g_kd[BH*SS];
__device__ float g_kdmax[BH];
__device__ float g_tls[BH*SS];
__device__ int   g_mark[BH*SS];

// ---------------- 128x128x16 NT GEMM core: C = A(MxK) * B(NxK)^T -------------
__device__ __forceinline__ void gemm128_nt(const float* __restrict__ Ap, int lda,
                                           const float* __restrict__ Bp, int ldb,
                                           int K, float (&acc)[8][8]) {
    __shared__ float As[16][132];
    __shared__ float Bs[16][132];
    int t = threadIdx.x;
    int tx = t & 15, ty = t >> 4;
    int lr = t >> 2, lk = (t & 3) * 4;
    for (int k0 = 0; k0 < K; k0 += 16) {
        float4 a0 = *(const float4*)(Ap + (size_t)lr * lda + k0 + lk);
        float4 a1 = *(const float4*)(Ap + (size_t)(lr + 64) * lda + k0 + lk);
        float4 b0 = *(const float4*)(Bp + (size_t)lr * ldb + k0 + lk);
        float4 b1 = *(const float4*)(Bp + (size_t)(lr + 64) * ldb + k0 + lk);
        __syncthreads();
        As[lk + 0][lr] = a0.x; As[lk + 1][lr] = a0.y; As[lk + 2][lr] = a0.z; As[lk + 3][lr] = a0.w;
        As[lk + 0][lr + 64] = a1.x; As[lk + 1][lr + 64] = a1.y; As[lk + 2][lr + 64] = a1.z; As[lk + 3][lr + 64] = a1.w;
        Bs[lk + 0][lr] = b0.x; Bs[lk + 1][lr] = b0.y; Bs[lk + 2][lr] = b0.z; Bs[lk + 3][lr] = b0.w;
        Bs[lk + 0][lr + 64] = b1.x; Bs[lk + 1][lr + 64] = b1.y; Bs[lk + 2][lr + 64] = b1.z; Bs[lk + 3][lr + 64] = b1.w;
        __syncthreads();
#pragma unroll
        for (int kk = 0; kk < 16; ++kk) {
            float av[8], bv[8];
            *(float4*)(av) = *(const float4*)&As[kk][tx * 4];
            *(float4*)(av + 4) = *(const float4*)&As[kk][tx * 4 + 64];
            *(float4*)(bv) = *(const float4*)&Bs[kk][ty * 4];
            *(float4*)(bv + 4) = *(const float4*)&Bs[kk][ty * 4 + 64];
#pragma unroll
            for (int i = 0; i < 8; i++)
#pragma unroll
                for (int j = 0; j < 8; j++) acc[i][j] += av[i] * bv[j];
        }
    }
}

__device__ __forceinline__ int row_of(int tx, int i) { return tx * 4 + (i < 4 ? i : 60 + i); }

// ---------------- K1: QKV GEMM -----------------------------------------------
__global__ __launch_bounds__(256) void qkv_gemm128(const float* __restrict__ x,
                                                   const float* __restrict__ w,
                                                   const float* __restrict__ bias) {
    int bx = blockIdx.x, by = blockIdx.y;
    float acc[8][8] = {};
    gemm128_nt(x + (size_t)by * 128 * DD, DD, w + (size_t)bx * 128 * DD, DD, DD, acc);
    int t = threadIdx.x, tx = t & 15, ty = t >> 4;
#pragma unroll
    for (int i = 0; i < 8; i++) {
        int m = by * 128 + row_of(tx, i);
        int b = m >> 11, s = m & (SS - 1);
#pragma unroll
        for (int j = 0; j < 8; j++) {
            int n = bx * 128 + row_of(ty, j);
            float v = acc[i][j] + bias[n];
            int which = n >> 10, h = (n >> 6) & 15, d = n & 63;
            float* dst = (which == 0) ? g_q : (which == 1) ? g_k : g_v;
            dst[((size_t)((b * HH + h) * SS + s)) * HD + d] = v;
        }
    }
}

// ---------------- K2: stats (centroid, sq, d2c) ------------------------------
__global__ __launch_bounds__(256) void stats_kernel(const float* __restrict__ x) {
    int bh = blockIdx.x;
    int b = bh / HH, h = bh % HH;
    int t = threadIdx.x;
    __shared__ float part[256];
    __shared__ float cent[64];
    int d = t & 63, grp = t >> 6;
    float acc = 0.f;
    for (int s = grp; s < SS; s += 4)
        acc += x[((size_t)(b * SS + s)) * DD + h * HD + d];
    part[t] = acc;
    __syncthreads();
    if (t < 64) cent[t] = (part[t] + part[t + 64] + part[t + 128] + part[t + 192]) * (1.0f / SS);
    __syncthreads();
    float lmax = 0.f;
    for (int s = t; s < SS; s += 256) {
        const float* xp = x + (size_t)(b * SS + s) * DD + h * HD;
        float sq = 0.f, dc2 = 0.f;
#pragma unroll
        for (int dd = 0; dd < HD; ++dd) {
            float v = xp[dd];
            sq += v * v;
            float wv = v - cent[dd];
            dc2 += wv * wv;
        }
        g_sq[bh * SS + s] = sq;
        float dc = sqrtf(dc2);
        g_d2c[bh * SS + s] = dc;
        lmax = fmaxf(lmax, dc);
    }
    __syncthreads();
    part[t] = lmax;
    __syncthreads();
    for (int off = 128; off > 0; off >>= 1) {
        if (t < off) part[t] = fmaxf(part[t], part[t + off]);
        __syncthreads();
    }
    if (t == 0) {
        g_d2cmax[bh] = part[0];
        g_kdmax[bh] = 0.f;
    }
}

// ---------------- K3: pairwise dist^2 into attn scratch ----------------------
__global__ __launch_bounds__(256) void dist_gemm128(const float* __restrict__ x,
                                                    float* __restrict__ dist2) {
    int bh = blockIdx.z;
    const float* base = x + (size_t)(bh >> 4) * SS * DD + (bh & 15) * HD;
    int bx = blockIdx.x, by = blockIdx.y;
    float acc[8][8] = {};
    gemm128_nt(base + (size_t)by * 128 * DD, DD, base + (size_t)bx * 128 * DD, DD, HD, acc);
    int t = threadIdx.x, tx = t & 15, ty = t >> 4;
#pragma unroll
    for (int i = 0; i < 8; i++) {
        int m = by * 128 + row_of(tx, i);
        float sqi = g_sq[bh * SS + m];
#pragma unroll
        for (int jg = 0; jg < 2; jg++) {
            int n0 = bx * 128 + ty * 4 + jg * 64;
            float4 sqj = *(const float4*)&g_sq[bh * SS + n0];
            float4 o;
            o.x = fmaxf(sqi + sqj.x - 2.f * acc[i][jg * 4 + 0], 0.f);
            o.y = fmaxf(sqi + sqj.y - 2.f * acc[i][jg * 4 + 1], 0.f);
            o.z = fmaxf(sqi + sqj.z - 2.f * acc[i][jg * 4 + 2], 0.f);
            o.w = fmaxf(sqi + sqj.w - 2.f * acc[i][jg * 4 + 3], 0.f);
            *(float4*)&dist2[((size_t)bh * SS + m) * SS + n0] = o;
        }
    }
}

// ---------------- K4: 10th-smallest per row (warp per row) -------------------
__global__ __launch_bounds__(256) void kth_kernel(const float* __restrict__ dist2) {
    int t = threadIdx.x, w = t >> 5, lane = t & 31;
    int s = blockIdx.x * 8 + w;
    int bh = blockIdx.y;
    const float* row = dist2 + ((size_t)bh * SS + s) * SS;
    float ls[10];
#pragma unroll
    for (int q = 0; q < 10; q++) ls[q] = 1e30f;
#pragma unroll 4
    for (int it = 0; it < 64; ++it) {
        float v = row[lane + it * 32];
        if (v < ls[9]) {
            ls[9] = v;
#pragma unroll
            for (int q = 9; q > 0; --q) {
                if (ls[q] < ls[q - 1]) { float tm = ls[q]; ls[q] = ls[q - 1]; ls[q - 1] = tm; }
            }
        }
    }
    float head = ls[0];
    float kth = 0.f;
#pragma unroll
    for (int r = 0; r < 10; ++r) {
        float m = head;
#pragma unroll
        for (int off = 16; off; off >>= 1) m = fminf(m, __shfl_xor_sync(0xffffffffu, m, off));
        kth = m;
        unsigned bal = __ballot_sync(0xffffffffu, head == m);
        if (lane == (__ffs(bal) - 1)) {
#pragma unroll
            for (int q = 0; q < 9; ++q) ls[q] = ls[q + 1];
            ls[9] = 1e30f;
            head = ls[0];
        }
    }
    if (lane == 0) {
        float kd = sqrtf(kth);
        g_kd[bh * SS + s] = kd;
        atomicMax((int*)&g_kdmax[bh], __float_as_int(kd));
    }
}

// ---------------- K5: tls ----------------------------------------------------
__global__ __launch_bounds__(256) void tls_kernel() {
    int bh = blockIdx.x;
    int t = threadIdx.x;
    float dinv = 1.0f / (g_d2cmax[bh] + 1e-8f);
    float kinv = 1.0f / (g_kdmax[bh] + 1e-8f);
    for (int s = t; s < SS; s += 256) {
        float life = g_d2c[bh * SS + s] * dinv;
        float mmd = g_kd[bh * SS + s] * kinv;
        g_tls[bh * SS + s] = 0.7f * life + 0.3f * mmd;
    }
}

// ---------------- K6: bitonic sort + mark ------------------------------------
__global__ __launch_bounds__(1024) void sort_mark_kernel() {
    __shared__ float a[SS];
    int t = threadIdx.x;
    int bh = blockIdx.x;
    a[t] = g_tls[bh * SS + t];
    a[t + 1024] = g_tls[bh * SS + t + 1024];
    __syncthreads();
    for (int k = 2; k <= SS; k <<= 1) {
        for (int j = k >> 1; j > 0; j >>= 1) {
#pragma unroll
            for (int half = 0; half < 2; ++half) {
                int i = t + half * 1024;
                int ixj = i ^ j;
                if (ixj > i) {
                    bool up = ((i & k) == 0);
                    float xi = a[i], xj = a[ixj];
                    if (up ? (xi > xj) : (xi < xj)) { a[i] = xj; a[ixj] = xi; }
                }
            }
            __syncthreads();
        }
    }
    float thresh = a[SS - NKEEP];
    __syncthreads();
#pragma unroll
    for (int half = 0; half < 2; ++half) {
        int s = t + half * 1024;
        g_mark[bh * SS + s] = (g_tls[bh * SS + s] >= thresh) ? 1 : 0;
    }
}

// ---------------- K7: score GEMM Q K^T * scale -------------------------------
__global__ __launch_bounds__(256) void score_gemm128(float* __restrict__ attn) {
    int bh = blockIdx.z;
    const float* qb = g_q + (size_t)bh * SS * HD;
    const float* kb = g_k + (size_t)bh * SS * HD;
    int bx = blockIdx.x, by = blockIdx.y;
    float acc[8][8] = {};
    gemm128_nt(qb + (size_t)by * 128 * HD, HD, kb + (size_t)bx * 128 * HD, HD, HD, acc);
    int t = threadIdx.x, tx = t & 15, ty = t >> 4;
    const float scale = 0.125f;
#pragma unroll
    for (int i = 0; i < 8; i++) {
        int m = by * 128 + row_of(tx, i);
#pragma unroll
        for (int jg = 0; jg < 2; jg++) {
            int n0 = bx * 128 + ty * 4 + jg * 64;
            float4 o;
            o.x = acc[i][jg * 4 + 0] * scale;
            o.y = acc[i][jg * 4 + 1] * scale;
            o.z = acc[i][jg * 4 + 2] * scale;
            o.w = acc[i][jg * 4 + 3] * scale;
            *(float4*)&attn[((size_t)bh * SS + m) * SS + n0] = o;
        }
    }
}

// ---------------- K8: masked softmax (warp per row, smem row buffer) ---------
__global__ __launch_bounds__(256) void softmax_kernel(float* __restrict__ attn) {
    extern __shared__ float smem[];
    float* rows = smem;                                  // 8 * SS
    unsigned char* mk = (unsigned char*)(rows + 8 * SS); // SS
    int bh = blockIdx.y;
    int t = threadIdx.x, w = t >> 5, lane = t & 31;
    int i = blockIdx.x * 8 + w;
    for (int j = t; j < SS; j += 256) mk[j] = (unsigned char)g_mark[bh * SS + j];
    float* gp = attn + ((size_t)bh * SS + i) * SS;
    float* rb = rows + w * SS;
    for (int it = 0; it < 64; ++it) rb[lane + it * 32] = gp[lane + it * 32];
    __syncthreads();
    float m = -1e30f;
    for (int it = 0; it < 64; ++it) {
        int j = lane + it * 32;
        int rel = j - i;
        bool ms = (rel >= -W2 && rel <= W2) || mk[j];
        if (ms) m = fmaxf(m, rb[j]);
    }
#pragma unroll
    for (int off = 16; off; off >>= 1) m = fmaxf(m, __shfl_xor_sync(0xffffffffu, m, off));
    float sum = 0.f;
    for (int it = 0; it < 64; ++it) {
        int j = lane + it * 32;
        int rel = j - i;
        bool ms = (rel >= -W2 && rel <= W2) || mk[j];
        if (ms) sum += __expf(rb[j] - m);
    }
#pragma unroll
    for (int off = 16; off; off >>= 1) sum += __shfl_xor_sync(0xffffffffu, sum, off);
    float inv = 1.0f / sum;
    for (int it = 0; it < 64; ++it) {
        int j = lane + it * 32;
        int rel = j - i;
        bool ms = (rel >= -W2 && rel <= W2) || mk[j];
        gp[j] = ms ? __expf(rb[j] - m) * inv : 0.f;
    }
}

// ---------------- K9: AV GEMM (NN): out = attn(2048x2048) @ V(2048x64) -------
__global__ __launch_bounds__(256) void av_gemm128(const float* __restrict__ attn) {
    __shared__ float As[16][132];
    __shared__ float Bs[16][68];
    int bh = blockIdx.y;
    int bx = blockIdx.x;
    const float* Ap = attn + ((size_t)bh * SS + bx * 128) * SS;
    const float* Bp = g_v + (size_t)bh * SS * HD;
    int t = threadIdx.x;
    int tx = t & 15, ty = t >> 4;
    int lr = t >> 2, lk = (t & 3) * 4;
    int rb2 = t >> 4, cb = (t & 15) * 4;
    float acc[8][4] = {};
    for (int k0 = 0; k0 < SS; k0 += 16) {
        float4 a0 = *(const float4*)(Ap + (size_t)lr * SS + k0 + lk);
        float4 a1 = *(const float4*)(Ap + (size_t)(lr + 64) * SS + k0 + lk);
        float4 bq = *(const float4*)(Bp + (size_t)(k0 + rb2) * HD + cb);
        __syncthreads();
        As[lk + 0][lr] = a0.x; As[lk + 1][lr] = a0.y; As[lk + 2][lr] = a0.z; As[lk + 3][lr] = a0.w;
        As[lk + 0][lr + 64] = a1.x; As[lk + 1][lr + 64] = a1.y; As[lk + 2][lr + 64] = a1.z; As[lk + 3][lr + 64] = a1.w;
        *(float4*)&Bs[rb2][cb] = bq;
        __syncthreads();
#pragma unroll
        for (int kk = 0; kk < 16; ++kk) {
            float av[8], bv[4];
            *(float4*)(av) = *(const float4*)&As[kk][tx * 4];
            *(float4*)(av + 4) = *(const float4*)&As[kk][tx * 4 + 64];
            *(float4*)(bv) = *(const float4*)&Bs[kk][ty * 4];
#pragma unroll
            for (int i = 0; i < 8; i++)
#pragma unroll
                for (int j = 0; j < 4; j++) acc[i][j] += av[i] * bv[j];
        }
    }
    int b = bh >> 4, h = bh & 15;
    int n0 = ty * 4;
#pragma unroll
    for (int i = 0; i < 8; i++) {
        int s = bx * 128 + row_of(tx, i);
        float4 o;
        o.x = acc[i][0]; o.y = acc[i][1]; o.z = acc[i][2]; o.w = acc[i][3];
        *(float4*)&g_o[((size_t)(b * SS + s)) * DD + h * 64 + n0] = o;
    }
}

// ---------------- K10: output projection -------------------------------------
__global__ __launch_bounds__(256) void proj_gemm128(const float* __restrict__ w,
                                                    const float* __restrict__ bias,
                                                    float* __restrict__ out) {
    int bx = blockIdx.x, by = blockIdx.y;
    float acc[8][8] = {};
    gemm128_nt(g_o + (size_t)by * 128 * DD, DD, w + (size_t)bx * 128 * DD, DD, DD, acc);
    int t = threadIdx.x, tx = t & 15, ty = t >> 4;
#pragma unroll
    for (int i = 0; i < 8; i++) {
        int m = by * 128 + row_of(tx, i);
#pragma unroll
        for (int jg = 0; jg < 2; jg++) {
            int n0 = bx * 128 + ty * 4 + jg * 64;
            float4 bi = *(const float4*)&bias[n0];
            float4 o;
            o.x = acc[i][jg * 4 + 0] + bi.x;
            o.y = acc[i][jg * 4 + 1] + bi.y;
            o.z = acc[i][jg * 4 + 2] + bi.z;
            o.w = acc[i][jg * 4 + 3] + bi.w;
            *(float4*)&out[(size_t)m * DD + n0] = o;
        }
    }
}

// ---------------- launch ------------------------------------------------------
extern "C" void kernel_launch(void* const* d_in, const int* in_sizes, int n_in,
                              void* d_out, int out_size) {
    const float* x = (const float*)d_in[0];
    const float* qkv_w = (const float*)d_in[1];
    const float* qkv_b = (const float*)d_in[2];
    const float* out_w = (const float*)d_in[3];
    const float* out_b = (const float*)d_in[4];
    float* out = (float*)d_out;
    float* attn = out + (size_t)BB * SS * DD;

    const int SM_SMEM = 8 * SS * 4 + SS;  // 67584
    cudaFuncSetAttribute(softmax_kernel, cudaFuncAttributeMaxDynamicSharedMemorySize, SM_SMEM);

    qkv_gemm128<<<dim3(24, 32), 256>>>(x, qkv_w, qkv_b);
    stats_kernel<<<BH, 256>>>(x);
    dist_gemm128<<<dim3(16, 16, BH), 256>>>(x, attn);
    kth_kernel<<<dim3(SS / 8, BH), 256>>>(attn);
    tls_kernel<<<BH, 256>>>();
    sort_mark_kernel<<<BH, 1024>>>();
    score_gemm128<<<dim3(16, 16, BH), 256>>>(attn);
    softmax_kernel<<<dim3(SS / 8, BH), 256, SM_SMEM>>>(attn);
    av_gemm128<<<dim3(16, BH), 256>>>(attn);
    proj_gemm128<<<dim3(8, 32), 256>>>(out_w, out_b, out);
}

// round 5
// speedup vs baseline: 4.1905x; 1.3778x over previous
#include <cuda_runtime.h>
#include <cuda_bf16.h>
#include <math.h>
#include <stdint.h>

#define BB 2
#define SS 2048
#define DD 1024
#define HH 16
#define HD 64
#define BH (BB*HH)
#define NKEEP 675
#define W2 64
#define SA 36  // smem row stride in bf16 units

// ---------------- scratch -----------------------------------------------------
__device__ float g_sq[BH*SS];
__device__ float g_d2c[BH*SS];
__device__ float g_d2cmax[BH];
__device__ float g_kd[BH*SS];
__device__ float g_kdmax[BH];
__device__ float g_tls[BH*SS];
__device__ int   g_mark[BH*SS];

__device__ __align__(256) __nv_bfloat16 g_xhi[BB*SS*DD];
__device__ __align__(256) __nv_bfloat16 g_xlo[BB*SS*DD];
__device__ __align__(256) __nv_bfloat16 g_w3hi[3*DD*DD];
__device__ __align__(256) __nv_bfloat16 g_w3lo[3*DD*DD];
__device__ __align__(256) __nv_bfloat16 g_w1hi[DD*DD];
__device__ __align__(256) __nv_bfloat16 g_w1lo[DD*DD];
__device__ __align__(256) __nv_bfloat16 g_qhi[BH*SS*HD];
__device__ __align__(256) __nv_bfloat16 g_qlo[BH*SS*HD];
__device__ __align__(256) __nv_bfloat16 g_khi[BH*SS*HD];
__device__ __align__(256) __nv_bfloat16 g_klo[BH*SS*HD];
__device__ __align__(256) __nv_bfloat16 g_vthi[BH*HD*SS];  // V^T: [bh][d][s]
__device__ __align__(256) __nv_bfloat16 g_vtlo[BH*HD*SS];
__device__ __align__(256) __nv_bfloat16 g_ohi[BB*SS*DD];
__device__ __align__(256) __nv_bfloat16 g_olo[BB*SS*DD];

// ---------------- mma.sync helpers --------------------------------------------
__device__ __forceinline__ void mma16816(float* c, uint32_t a0, uint32_t a1, uint32_t a2,
                                         uint32_t a3, uint32_t b0, uint32_t b1) {
    asm volatile(
        "mma.sync.aligned.m16n8k16.row.col.f32.bf16.bf16.f32 "
        "{%0,%1,%2,%3}, {%4,%5,%6,%7}, {%8,%9}, {%0,%1,%2,%3};"
        : "+f"(c[0]), "+f"(c[1]), "+f"(c[2]), "+f"(c[3])
        : "r"(a0), "r"(a1), "r"(a2), "r"(a3), "r"(b0), "r"(b1));
}

__device__ __forceinline__ uint32_t packbf2(float x, float y) {
    __nv_bfloat162 h;
    h.x = __float2bfloat16(x);
    h.y = __float2bfloat16(y);
    return *(uint32_t*)&h;
}
__device__ __forceinline__ void split2(float x, float y, uint32_t& hi, uint32_t& lo) {
    __nv_bfloat16 hx = __float2bfloat16(x), hy = __float2bfloat16(y);
    __nv_bfloat162 h, l;
    h.x = hx; h.y = hy;
    l.x = __float2bfloat16(x - __bfloat162float(hx));
    l.y = __float2bfloat16(y - __bfloat162float(hy));
    hi = *(uint32_t*)&h;
    lo = *(uint32_t*)&l;
}

// stage a [rows x 32] bf16 tile into smem [rows][SA]
__device__ __forceinline__ void stage_bf(__nv_bfloat16* dst, const __nv_bfloat16* src,
                                         int ld, int k0, int t, int iters) {
#pragma unroll
    for (int i = 0; i < 4; i++) {
        if (i >= iters) break;
        int lin = t + i * 256;
        int r = lin >> 3, h = lin & 7;
        *(uint2*)&dst[r * SA + h * 4] = *(const uint2*)&src[(size_t)r * ld + k0 + h * 4];
    }
}
// stage a [128 x 32] fp32 tile as split bf16 hi/lo
__device__ __forceinline__ void stage_f32_split(__nv_bfloat16* dh, __nv_bfloat16* dl,
                                                const float* src, int ld, int k0, int t) {
#pragma unroll
    for (int i = 0; i < 8; i++) {
        int lin = t + i * 256;
        int r = lin >> 4, h = lin & 15;
        float2 v = *(const float2*)&src[(size_t)r * ld + k0 + h * 2];
        uint32_t hi, lo;
        split2(v.x, v.y, hi, lo);
        *(uint32_t*)&dh[r * SA + h * 2] = hi;
        *(uint32_t*)&dl[r * SA + h * 2] = lo;
    }
}

// core: 128x128 output, 8 warps, warp tile 64x32; acc[mt][nt][4]
__device__ __forceinline__ void mma_steps(const __nv_bfloat16* As, const __nv_bfloat16* Bs,
                                          int wm, int wn, int g, int tg, float (*acc)[4][4]) {
#pragma unroll
    for (int s = 0; s < 2; s++) {
        int kk = s * 16;
        uint32_t afr[4][4];
#pragma unroll
        for (int mt = 0; mt < 4; mt++) {
            int r0 = (wm + mt * 16 + g) * SA + kk + tg * 2;
            afr[mt][0] = *(const uint32_t*)&As[r0];
            afr[mt][1] = *(const uint32_t*)&As[r0 + 8 * SA];
            afr[mt][2] = *(const uint32_t*)&As[r0 + 8];
            afr[mt][3] = *(const uint32_t*)&As[r0 + 8 * SA + 8];
        }
#pragma unroll
        for (int nt = 0; nt < 4; nt++) {
            int rb = (wn + nt * 8 + g) * SA + kk + tg * 2;
            uint32_t b0 = *(const uint32_t*)&Bs[rb];
            uint32_t b1 = *(const uint32_t*)&Bs[rb + 8];
#pragma unroll
            for (int mt = 0; mt < 4; mt++)
                mma16816(acc[mt][nt], afr[mt][0], afr[mt][1], afr[mt][2], afr[mt][3], b0, b1);
        }
    }
}

#define GEMM_PROLOG() \
    __shared__ __nv_bfloat16 sAh[128 * SA], sAl[128 * SA], sBh[128 * SA], sBl[128 * SA]; \
    int t = threadIdx.x, w = t >> 5, lane = t & 31; \
    int wm = (w & 1) * 64, wn = (w >> 1) * 32; \
    int g = lane >> 2, tg = lane & 3; \
    float acc[4][4][4] = {};

#define GEMM_LOOP(Ahi, Alo, lda, Bhi, Blo, ldb, K, NPASS) \
    for (int k0 = 0; k0 < (K); k0 += 32) { \
        __syncthreads(); \
        stage_bf(sAh, (Ahi), (lda), k0, t, 4); \
        stage_bf(sAl, (Alo), (lda), k0, t, 4); \
        stage_bf(sBh, (Bhi), (ldb), k0, t, 4); \
        stage_bf(sBl, (Blo), (ldb), k0, t, 4); \
        __syncthreads(); \
        for (int p = 0; p < (NPASS); p++) \
            mma_steps((p & 2) ? sAl : sAh, (p & 1) ? sBl : sBh, wm, wn, g, tg, acc); \
    }

// ---------------- cvt: fp32 -> (hi, lo) bf16 ----------------------------------
__global__ __launch_bounds__(256) void cvt_x(const float* __restrict__ s) {
    int i = blockIdx.x * 256 + threadIdx.x;
    if (i < BB * SS * DD) {
        float v = s[i];
        __nv_bfloat16 h = __float2bfloat16(v);
        g_xhi[i] = h;
        g_xlo[i] = __float2bfloat16(v - __bfloat162float(h));
    }
}
__global__ __launch_bounds__(256) void cvt_w3(const float* __restrict__ s) {
    int i = blockIdx.x * 256 + threadIdx.x;
    if (i < 3 * DD * DD) {
        float v = s[i];
        __nv_bfloat16 h = __float2bfloat16(v);
        g_w3hi[i] = h;
        g_w3lo[i] = __float2bfloat16(v - __bfloat162float(h));
    }
}
__global__ __launch_bounds__(256) void cvt_w1(const float* __restrict__ s) {
    int i = blockIdx.x * 256 + threadIdx.x;
    if (i < DD * DD) {
        float v = s[i];
        __nv_bfloat16 h = __float2bfloat16(v);
        g_w1hi[i] = h;
        g_w1lo[i] = __float2bfloat16(v - __bfloat162float(h));
    }
}

// ---------------- K1: QKV GEMM (mma) ------------------------------------------
__global__ __launch_bounds__(256) void qkv_mma(const float* __restrict__ bias) {
    GEMM_PROLOG();
    int bx = blockIdx.x, by = blockIdx.y;
    GEMM_LOOP(g_xhi + (size_t)by * 128 * DD, g_xlo + (size_t)by * 128 * DD, DD,
              g_w3hi + (size_t)bx * 128 * DD, g_w3lo + (size_t)bx * 128 * DD, DD, DD, 3);
#pragma unroll
    for (int mt = 0; mt < 4; mt++)
#pragma unroll
        for (int nt = 0; nt < 4; nt++) {
            float* c = acc[mt][nt];
#pragma unroll
            for (int half = 0; half < 2; half++) {
                int m = by * 128 + wm + mt * 16 + g + half * 8;
                int n = bx * 128 + wn + nt * 8 + tg * 2;
                float v0 = c[half * 2] + bias[n];
                float v1 = c[half * 2 + 1] + bias[n + 1];
                int which = n >> 10, h = (n >> 6) & 15, d = n & 63;
                int b = m >> 11, s = m & (SS - 1);
                int bh = b * HH + h;
                if (which == 0) {
                    size_t di = ((size_t)bh * SS + s) * HD + d;
                    uint32_t hi, lo;
                    split2(v0 * 0.125f, v1 * 0.125f, hi, lo);
                    *(uint32_t*)&g_qhi[di] = hi;
                    *(uint32_t*)&g_qlo[di] = lo;
                } else if (which == 1) {
                    size_t di = ((size_t)bh * SS + s) * HD + d;
                    uint32_t hi, lo;
                    split2(v0, v1, hi, lo);
                    *(uint32_t*)&g_khi[di] = hi;
                    *(uint32_t*)&g_klo[di] = lo;
                } else {
                    size_t di = ((size_t)bh * HD + d) * SS + s;
                    __nv_bfloat16 h0 = __float2bfloat16(v0), h1 = __float2bfloat16(v1);
                    g_vthi[di] = h0;
                    g_vtlo[di] = __float2bfloat16(v0 - __bfloat162float(h0));
                    g_vthi[di + SS] = h1;
                    g_vtlo[di + SS] = __float2bfloat16(v1 - __bfloat162float(h1));
                }
            }
        }
}

// ---------------- K3: pairwise dist^2 (mma, 4-pass) ---------------------------
__global__ __launch_bounds__(256) void dist_mma(float* __restrict__ dist2) {
    GEMM_PROLOG();
    int bx = blockIdx.x, by = blockIdx.y, bh = blockIdx.z;
    size_t base = (size_t)(bh >> 4) * SS * DD + (bh & 15) * HD;
    GEMM_LOOP(g_xhi + base + (size_t)by * 128 * DD, g_xlo + base + (size_t)by * 128 * DD, DD,
              g_xhi + base + (size_t)bx * 128 * DD, g_xlo + base + (size_t)bx * 128 * DD, DD, HD, 4);
    float* dbase = dist2 + (size_t)bh * SS * SS;
#pragma unroll
    for (int mt = 0; mt < 4; mt++)
#pragma unroll
        for (int nt = 0; nt < 4; nt++) {
            float* c = acc[mt][nt];
#pragma unroll
            for (int half = 0; half < 2; half++) {
                int m = by * 128 + wm + mt * 16 + g + half * 8;
                int n = bx * 128 + wn + nt * 8 + tg * 2;
                float sqi = g_sq[bh * SS + m];
                float2 o;
                o.x = fmaxf(sqi + g_sq[bh * SS + n] - 2.f * c[half * 2], 0.f);
                o.y = fmaxf(sqi + g_sq[bh * SS + n + 1] - 2.f * c[half * 2 + 1], 0.f);
                *(float2*)&dbase[(size_t)m * SS + n] = o;
            }
        }
}

// ---------------- K7: score GEMM (mma, scale folded into q) -------------------
__global__ __launch_bounds__(256) void score_mma(float* __restrict__ attn) {
    GEMM_PROLOG();
    int bx = blockIdx.x, by = blockIdx.y, bh = blockIdx.z;
    size_t qo = ((size_t)bh * SS + by * 128) * HD;
    size_t ko = ((size_t)bh * SS + bx * 128) * HD;
    GEMM_LOOP(g_qhi + qo, g_qlo + qo, HD, g_khi + ko, g_klo + ko, HD, HD, 3);
    float* abase = attn + (size_t)bh * SS * SS;
#pragma unroll
    for (int mt = 0; mt < 4; mt++)
#pragma unroll
        for (int nt = 0; nt < 4; nt++) {
            float* c = acc[mt][nt];
#pragma unroll
            for (int half = 0; half < 2; half++) {
                int m = by * 128 + wm + mt * 16 + g + half * 8;
                int n = bx * 128 + wn + nt * 8 + tg * 2;
                float2 o;
                o.x = c[half * 2];
                o.y = c[half * 2 + 1];
                *(float2*)&abase[(size_t)m * SS + n] = o;
            }
        }
}

// ---------------- K9: AV GEMM (mma, in-kernel attn split) ---------------------
__global__ __launch_bounds__(256) void av_mma(const float* __restrict__ attn) {
    __shared__ __nv_bfloat16 sAh[128 * SA], sAl[128 * SA];
    __shared__ __nv_bfloat16 sVh[64 * SA], sVl[64 * SA];
    int t = threadIdx.x, w = t >> 5, lane = t & 31;
    int wm = (w & 1) * 64, wn = (w >> 1) * 16;
    int g = lane >> 2, tg = lane & 3;
    int bx = blockIdx.x, bh = blockIdx.y;
    const float* Ap = attn + ((size_t)bh * SS + bx * 128) * SS;
    const __nv_bfloat16* Vh = g_vthi + (size_t)bh * HD * SS;
    const __nv_bfloat16* Vl = g_vtlo + (size_t)bh * HD * SS;
    float acc[4][2][4] = {};
    for (int k0 = 0; k0 < SS; k0 += 32) {
        __syncthreads();
        stage_f32_split(sAh, sAl, Ap, SS, k0, t);
        stage_bf(sVh, Vh, SS, k0, t, 2);
        stage_bf(sVl, Vl, SS, k0, t, 2);
        __syncthreads();
        for (int p = 0; p < 3; p++) {
            const __nv_bfloat16* As = (p & 2) ? sAl : sAh;
            const __nv_bfloat16* Bs = (p & 1) ? sVl : sVh;
#pragma unroll
            for (int s = 0; s < 2; s++) {
                int kk = s * 16;
                uint32_t afr[4][4];
#pragma unroll
                for (int mt = 0; mt < 4; mt++) {
                    int r0 = (wm + mt * 16 + g) * SA + kk + tg * 2;
                    afr[mt][0] = *(const uint32_t*)&As[r0];
                    afr[mt][1] = *(const uint32_t*)&As[r0 + 8 * SA];
                    afr[mt][2] = *(const uint32_t*)&As[r0 + 8];
                    afr[mt][3] = *(const uint32_t*)&As[r0 + 8 * SA + 8];
                }
#pragma unroll
                for (int nt = 0; nt < 2; nt++) {
                    int rb = (wn + nt * 8 + g) * SA + kk + tg * 2;
                    uint32_t b0 = *(const uint32_t*)&Bs[rb];
                    uint32_t b1 = *(const uint32_t*)&Bs[rb + 8];
#pragma unroll
                    for (int mt = 0; mt < 4; mt++)
                        mma16816(acc[mt][nt], afr[mt][0], afr[mt][1], afr[mt][2], afr[mt][3], b0, b1);
                }
            }
        }
    }
    int b = bh >> 4, h = bh & 15;
#pragma unroll
    for (int mt = 0; mt < 4; mt++)
#pragma unroll
        for (int nt = 0; nt < 2; nt++) {
            float* c = acc[mt][nt];
#pragma unroll
            for (int half = 0; half < 2; half++) {
                int s = bx * 128 + wm + mt * 16 + g + half * 8;
                int d = wn + nt * 8 + tg * 2;
                size_t di = ((size_t)(b * SS + s)) * DD + h * 64 + d;
                uint32_t hi, lo;
                split2(c[half * 2], c[half * 2 + 1], hi, lo);
                *(uint32_t*)&g_ohi[di] = hi;
                *(uint32_t*)&g_olo[di] = lo;
            }
        }
}

// ---------------- K10: output projection (mma) --------------------------------
__global__ __launch_bounds__(256) void proj_mma(const float* __restrict__ bias,
                                                float* __restrict__ out) {
    GEMM_PROLOG();
    int bx = blockIdx.x, by = blockIdx.y;
    GEMM_LOOP(g_ohi + (size_t)by * 128 * DD, g_olo + (size_t)by * 128 * DD, DD,
              g_w1hi + (size_t)bx * 128 * DD, g_w1lo + (size_t)bx * 128 * DD, DD, DD, 3);
#pragma unroll
    for (int mt = 0; mt < 4; mt++)
#pragma unroll
        for (int nt = 0; nt < 4; nt++) {
            float* c = acc[mt][nt];
#pragma unroll
            for (int half = 0; half < 2; half++) {
                int m = by * 128 + wm + mt * 16 + g + half * 8;
                int n = bx * 128 + wn + nt * 8 + tg * 2;
                float2 o;
                o.x = c[half * 2] + bias[n];
                o.y = c[half * 2 + 1] + bias[n + 1];
                *(float2*)&out[(size_t)m * DD + n] = o;
            }
        }
}

// ---------------- K2: stats ---------------------------------------------------
__global__ __launch_bounds__(256) void stats_kernel(const float* __restrict__ x) {
    int bh = blockIdx.x;
    int b = bh / HH, h = bh % HH;
    int t = threadIdx.x;
    __shared__ float part[256];
    __shared__ float cent[64];
    int d = t & 63, grp = t >> 6;
    float acc = 0.f;
    for (int s = grp; s < SS; s += 4)
        acc += x[((size_t)(b * SS + s)) * DD + h * HD + d];
    part[t] = acc;
    __syncthreads();
    if (t < 64) cent[t] = (part[t] + part[t + 64] + part[t + 128] + part[t + 192]) * (1.0f / SS);
    __syncthreads();
    float lmax = 0.f;
    for (int s = t; s < SS; s += 256) {
        const float* xp = x + (size_t)(b * SS + s) * DD + h * HD;
        float sq = 0.f, dc2 = 0.f;
#pragma unroll
        for (int dd = 0; dd < HD; ++dd) {
            float v = xp[dd];
            sq += v * v;
            float wv = v - cent[dd];
            dc2 += wv * wv;
        }
        g_sq[bh * SS + s] = sq;
        float dc = sqrtf(dc2);
        g_d2c[bh * SS + s] = dc;
        lmax = fmaxf(lmax, dc);
    }
    __syncthreads();
    part[t] = lmax;
    __syncthreads();
    for (int off = 128; off > 0; off >>= 1) {
        if (t < off) part[t] = fmaxf(part[t], part[t + off]);
        __syncthreads();
    }
    if (t == 0) {
        g_d2cmax[bh] = part[0];
        g_kdmax[bh] = 0.f;
    }
}

// ---------------- K4: 10th-smallest per row -----------------------------------
__global__ __launch_bounds__(256) void kth_kernel(const float* __restrict__ dist2) {
    int t = threadIdx.x, w = t >> 5, lane = t & 31;
    int s = blockIdx.x * 8 + w;
    int bh = blockIdx.y;
    const float* row = dist2 + ((size_t)bh * SS + s) * SS;
    float ls[10];
#pragma unroll
    for (int q = 0; q < 10; q++) ls[q] = 1e30f;
#pragma unroll 4
    for (int it = 0; it < 64; ++it) {
        float v = row[lane + it * 32];
        if (v < ls[9]) {
            ls[9] = v;
#pragma unroll
            for (int q = 9; q > 0; --q) {
                if (ls[q] < ls[q - 1]) { float tm = ls[q]; ls[q] = ls[q - 1]; ls[q - 1] = tm; }
            }
        }
    }
    float head = ls[0];
    float kth = 0.f;
#pragma unroll
    for (int r = 0; r < 10; ++r) {
        float m = head;
#pragma unroll
        for (int off = 16; off; off >>= 1) m = fminf(m, __shfl_xor_sync(0xffffffffu, m, off));
        kth = m;
        unsigned bal = __ballot_sync(0xffffffffu, head == m);
        if (lane == (__ffs(bal) - 1)) {
#pragma unroll
            for (int q = 0; q < 9; ++q) ls[q] = ls[q + 1];
            ls[9] = 1e30f;
            head = ls[0];
        }
    }
    if (lane == 0) {
        float kd = sqrtf(kth);
        g_kd[bh * SS + s] = kd;
        atomicMax((int*)&g_kdmax[bh], __float_as_int(kd));
    }
}

// ---------------- K5: tls -----------------------------------------------------
__global__ __launch_bounds__(256) void tls_kernel() {
    int bh = blockIdx.x;
    int t = threadIdx.x;
    float dinv = 1.0f / (g_d2cmax[bh] + 1e-8f);
    float kinv = 1.0f / (g_kdmax[bh] + 1e-8f);
    for (int s = t; s < SS; s += 256) {
        float life = g_d2c[bh * SS + s] * dinv;
        float mmd = g_kd[bh * SS + s] * kinv;
        g_tls[bh * SS + s] = 0.7f * life + 0.3f * mmd;
    }
}

// ---------------- K6: bitonic sort + mark -------------------------------------
__global__ __launch_bounds__(1024) void sort_mark_kernel() {
    __shared__ float a[SS];
    int t = threadIdx.x;
    int bh = blockIdx.x;
    a[t] = g_tls[bh * SS + t];
    a[t + 1024] = g_tls[bh * SS + t + 1024];
    __syncthreads();
    for (int k = 2; k <= SS; k <<= 1) {
        for (int j = k >> 1; j > 0; j >>= 1) {
#pragma unroll
            for (int half = 0; half < 2; ++half) {
                int i = t + half * 1024;
                int ixj = i ^ j;
                if (ixj > i) {
                    bool up = ((i & k) == 0);
                    float xi = a[i], xj = a[ixj];
                    if (up ? (xi > xj) : (xi < xj)) { a[i] = xj; a[ixj] = xi; }
                }
            }
            __syncthreads();
        }
    }
    float thresh = a[SS - NKEEP];
    __syncthreads();
#pragma unroll
    for (int half = 0; half < 2; ++half) {
        int s = t + half * 1024;
        g_mark[bh * SS + s] = (g_tls[bh * SS + s] >= thresh) ? 1 : 0;
    }
}

// ---------------- K8: masked softmax ------------------------------------------
__global__ __launch_bounds__(256) void softmax_kernel(float* __restrict__ attn) {
    extern __shared__ float smemf[];
    float* rows = smemf;
    unsigned char* mk = (unsigned char*)(rows + 8 * SS);
    int bh = blockIdx.y;
    int t = threadIdx.x, w = t >> 5, lane = t & 31;
    int i = blockIdx.x * 8 + w;
    for (int j = t; j < SS; j += 256) mk[j] = (unsigned char)g_mark[bh * SS + j];
    float* gp = attn + ((size_t)bh * SS + i) * SS;
    float* rb = rows + w * SS;
    for (int it = 0; it < 64; ++it) rb[lane + it * 32] = gp[lane + it * 32];
    __syncthreads();
    float m = -1e30f;
    for (int it = 0; it < 64; ++it) {
        int j = lane + it * 32;
        int rel = j - i;
        bool ms = (rel >= -W2 && rel <= W2) || mk[j];
        if (ms) m = fmaxf(m, rb[j]);
    }
#pragma unroll
    for (int off = 16; off; off >>= 1) m = fmaxf(m, __shfl_xor_sync(0xffffffffu, m, off));
    float sum = 0.f;
    for (int it = 0; it < 64; ++it) {
        int j = lane + it * 32;
        int rel = j - i;
        bool ms = (rel >= -W2 && rel <= W2) || mk[j];
        if (ms) sum += __expf(rb[j] - m);
    }
#pragma unroll
    for (int off = 16; off; off >>= 1) sum += __shfl_xor_sync(0xffffffffu, sum, off);
    float inv = 1.0f / sum;
    for (int it = 0; it < 64; ++it) {
        int j = lane + it * 32;
        int rel = j - i;
        bool ms = (rel >= -W2 && rel <= W2) || mk[j];
        gp[j] = ms ? __expf(rb[j] - m) * inv : 0.f;
    }
}

// ---------------- launch ------------------------------------------------------
extern "C" void kernel_launch(void* const* d_in, const int* in_sizes, int n_in,
                              void* d_out, int out_size) {
    const float* x = (const float*)d_in[0];
    const float* qkv_w = (const float*)d_in[1];
    const float* qkv_b = (const float*)d_in[2];
    const float* out_w = (const float*)d_in[3];
    const float* out_b = (const float*)d_in[4];
    float* out = (float*)d_out;
    float* attn = out + (size_t)BB * SS * DD;

    const int SM_SMEM = 8 * SS * 4 + SS;
    cudaFuncSetAttribute(softmax_kernel, cudaFuncAttributeMaxDynamicSharedMemorySize, SM_SMEM);

    cvt_x<<<(BB * SS * DD + 255) / 256, 256>>>(x);
    cvt_w3<<<(3 * DD * DD + 255) / 256, 256>>>(qkv_w);
    cvt_w1<<<(DD * DD + 255) / 256, 256>>>(out_w);

    qkv_mma<<<dim3(24, 32), 256>>>(qkv_b);
    stats_kernel<<<BH, 256>>>(x);
    dist_mma<<<dim3(16, 16, BH), 256>>>(attn);
    kth_kernel<<<dim3(SS / 8, BH), 256>>>(attn);
    tls_kernel<<<BH, 256>>>();
    sort_mark_kernel<<<BH, 1024>>>();
    score_mma<<<dim3(16, 16, BH), 256>>>(attn);
    softmax_kernel<<<dim3(SS / 8, BH), 256, SM_SMEM>>>(attn);
    av_mma<<<dim3(16, BH), 256>>>(attn);
    proj_mma<<<dim3(8, 32), 256>>>(out_b, out);
}

// round 6
// speedup vs baseline: 4.2214x; 1.0074x over previous
#include <cuda_runtime.h>
#include <cuda_bf16.h>
#include <math.h>
#include <stdint.h>

#define BB 2
#define SS 2048
#define DD 1024
#define HH 16
#define HD 64
#define BH (BB*HH)
#define NKEEP 675
#define W2 64
#define SA 36   // smem row stride (bf16) for 32-wide K chunks
#define SA2 68  // smem row stride (bf16) for 64-wide K chunks

// ---------------- scratch -----------------------------------------------------
__device__ float g_sq[BH*SS];
__device__ float g_d2c[BH*SS];
__device__ float g_d2cmax[BH];
__device__ float g_kd[BH*SS];
__device__ float g_kdmax[BH];
__device__ float g_tls[BH*SS];
__device__ int   g_mark[BH*SS];

__device__ __align__(256) __nv_bfloat16 g_xhi[BB*SS*DD];
__device__ __align__(256) __nv_bfloat16 g_xlo[BB*SS*DD];
__device__ __align__(256) __nv_bfloat16 g_w3hi[3*DD*DD];
__device__ __align__(256) __nv_bfloat16 g_w3lo[3*DD*DD];
__device__ __align__(256) __nv_bfloat16 g_w1hi[DD*DD];
__device__ __align__(256) __nv_bfloat16 g_w1lo[DD*DD];
__device__ __align__(256) __nv_bfloat16 g_qhi[BH*SS*HD];
__device__ __align__(256) __nv_bfloat16 g_qlo[BH*SS*HD];
__device__ __align__(256) __nv_bfloat16 g_khi[BH*SS*HD];
__device__ __align__(256) __nv_bfloat16 g_klo[BH*SS*HD];
__device__ __align__(256) __nv_bfloat16 g_vthi[BH*HD*SS];  // V^T: [bh][d][s]
__device__ __align__(256) __nv_bfloat16 g_vtlo[BH*HD*SS];
__device__ __align__(256) __nv_bfloat16 g_ohi[BB*SS*DD];
__device__ __align__(256) __nv_bfloat16 g_olo[BB*SS*DD];

// ---------------- helpers -----------------------------------------------------
__device__ __forceinline__ uint32_t s2u(const void* p) {
    uint32_t a;
    asm("{ .reg .u64 t; cvta.to.shared.u64 t, %1; cvt.u32.u64 %0, t; }" : "=r"(a) : "l"(p));
    return a;
}
__device__ __forceinline__ void mma16816(float* c, uint32_t a0, uint32_t a1, uint32_t a2,
                                         uint32_t a3, uint32_t b0, uint32_t b1) {
    asm volatile(
        "mma.sync.aligned.m16n8k16.row.col.f32.bf16.bf16.f32 "
        "{%0,%1,%2,%3}, {%4,%5,%6,%7}, {%8,%9}, {%0,%1,%2,%3};"
        : "+f"(c[0]), "+f"(c[1]), "+f"(c[2]), "+f"(c[3])
        : "r"(a0), "r"(a1), "r"(a2), "r"(a3), "r"(b0), "r"(b1));
}
__device__ __forceinline__ void split2(float x, float y, uint32_t& hi, uint32_t& lo) {
    __nv_bfloat16 hx = __float2bfloat16(x), hy = __float2bfloat16(y);
    __nv_bfloat162 h, l;
    h.x = hx; h.y = hy;
    l.x = __float2bfloat16(x - __bfloat162float(hx));
    l.y = __float2bfloat16(y - __bfloat162float(hy));
    hi = *(uint32_t*)&h;
    lo = *(uint32_t*)&l;
}
__device__ __forceinline__ void cp8(__nv_bfloat16* dst, const __nv_bfloat16* src) {
    uint32_t d = s2u(dst);
    asm volatile("cp.async.ca.shared.global [%0], [%1], 8;" :: "r"(d), "l"(src) : "memory");
}
#define CP_COMMIT() asm volatile("cp.async.commit_group;" ::: "memory")
#define CP_WAIT1() asm volatile("cp.async.wait_group 1;" ::: "memory")
#define CP_WAIT0() asm volatile("cp.async.wait_group 0;" ::: "memory")

// cp.async stage of a [128 x 32] bf16 tile -> smem [128][SA]
__device__ __forceinline__ void stage_cp(__nv_bfloat16* dst, const __nv_bfloat16* src,
                                         int ld, int k0, int t) {
#pragma unroll
    for (int i = 0; i < 4; i++) {
        int lin = t + i * 256;
        int r = lin >> 3, h = lin & 7;
        cp8(&dst[r * SA + h * 4], &src[(size_t)r * ld + k0 + h * 4]);
    }
}
// cp.async stage of a [128 x 64] bf16 tile -> smem [128][SA2]
__device__ __forceinline__ void stage_cp64(__nv_bfloat16* dst, const __nv_bfloat16* src,
                                           int ld, int t) {
#pragma unroll
    for (int i = 0; i < 8; i++) {
        int lin = t + i * 256;
        int r = lin >> 4, h = lin & 15;
        cp8(&dst[r * SA2 + h * 4], &src[(size_t)r * ld + h * 4]);
    }
}
// sync stage of a [rows x 32] bf16 tile (av kernel)
__device__ __forceinline__ void stage_bf(__nv_bfloat16* dst, const __nv_bfloat16* src,
                                         int ld, int k0, int t, int iters) {
#pragma unroll
    for (int i = 0; i < 4; i++) {
        if (i >= iters) break;
        int lin = t + i * 256;
        int r = lin >> 3, h = lin & 7;
        *(uint2*)&dst[r * SA + h * 4] = *(const uint2*)&src[(size_t)r * ld + k0 + h * 4];
    }
}
// stage [128 x 32] fp32 tile as split bf16 hi/lo (av kernel)
__device__ __forceinline__ void stage_f32_split(__nv_bfloat16* dh, __nv_bfloat16* dl,
                                                const float* src, int ld, int k0, int t) {
#pragma unroll
    for (int i = 0; i < 8; i++) {
        int lin = t + i * 256;
        int r = lin >> 4, h = lin & 15;
        float2 v = *(const float2*)&src[(size_t)r * ld + k0 + h * 2];
        uint32_t hi, lo;
        split2(v.x, v.y, hi, lo);
        *(uint32_t*)&dh[r * SA + h * 2] = hi;
        *(uint32_t*)&dl[r * SA + h * 2] = lo;
    }
}

// mma over one 32-K chunk (stride SA); warp tile 64x32, acc[4][4][4]
__device__ __forceinline__ void mma_steps(const __nv_bfloat16* As, const __nv_bfloat16* Bs,
                                          int wm, int wn, int g, int tg, float (*acc)[4][4]) {
#pragma unroll
    for (int s = 0; s < 2; s++) {
        int kk = s * 16;
        uint32_t afr[4][4];
#pragma unroll
        for (int mt = 0; mt < 4; mt++) {
            int r0 = (wm + mt * 16 + g) * SA + kk + tg * 2;
            afr[mt][0] = *(const uint32_t*)&As[r0];
            afr[mt][1] = *(const uint32_t*)&As[r0 + 8 * SA];
            afr[mt][2] = *(const uint32_t*)&As[r0 + 8];
            afr[mt][3] = *(const uint32_t*)&As[r0 + 8 * SA + 8];
        }
#pragma unroll
        for (int nt = 0; nt < 4; nt++) {
            int rb = (wn + nt * 8 + g) * SA + kk + tg * 2;
            uint32_t b0 = *(const uint32_t*)&Bs[rb];
            uint32_t b1 = *(const uint32_t*)&Bs[rb + 8];
#pragma unroll
            for (int mt = 0; mt < 4; mt++)
                mma16816(acc[mt][nt], afr[mt][0], afr[mt][1], afr[mt][2], afr[mt][3], b0, b1);
        }
    }
}
// mma over one 64-K chunk (stride SA2)
__device__ __forceinline__ void mma_steps64(const __nv_bfloat16* As, const __nv_bfloat16* Bs,
                                            int wm, int wn, int g, int tg, float (*acc)[4][4]) {
#pragma unroll
    for (int s = 0; s < 4; s++) {
        int kk = s * 16;
        uint32_t afr[4][4];
#pragma unroll
        for (int mt = 0; mt < 4; mt++) {
            int r0 = (wm + mt * 16 + g) * SA2 + kk + tg * 2;
            afr[mt][0] = *(const uint32_t*)&As[r0];
            afr[mt][1] = *(const uint32_t*)&As[r0 + 8 * SA2];
            afr[mt][2] = *(const uint32_t*)&As[r0 + 8];
            afr[mt][3] = *(const uint32_t*)&As[r0 + 8 * SA2 + 8];
        }
#pragma unroll
        for (int nt = 0; nt < 4; nt++) {
            int rb = (wn + nt * 8 + g) * SA2 + kk + tg * 2;
            uint32_t b0 = *(const uint32_t*)&Bs[rb];
            uint32_t b1 = *(const uint32_t*)&Bs[rb + 8];
#pragma unroll
            for (int mt = 0; mt < 4; mt++)
                mma16816(acc[mt][nt], afr[mt][0], afr[mt][1], afr[mt][2], afr[mt][3], b0, b1);
        }
    }
}

// double-buffered mainloop (tiles: 0=Ahi 1=Alo 2=Bhi 3=Blo; 9216B each)
#define TILE_BYTES 9216
__device__ __forceinline__ void gemm_db(const __nv_bfloat16* Ahi, const __nv_bfloat16* Alo, int lda,
                                        const __nv_bfloat16* Bhi, const __nv_bfloat16* Blo, int ldb,
                                        int K, int npass, char* dsm, int t, int wm, int wn,
                                        int g, int tg, float (*acc)[4][4]) {
    auto tile = [&](int buf, int idx) {
        return (__nv_bfloat16*)(dsm + (buf * 4 + idx) * TILE_BYTES);
    };
    stage_cp(tile(0, 0), Ahi, lda, 0, t);
    stage_cp(tile(0, 1), Alo, lda, 0, t);
    stage_cp(tile(0, 2), Bhi, ldb, 0, t);
    stage_cp(tile(0, 3), Blo, ldb, 0, t);
    CP_COMMIT();
    int nch = K / 32;
    for (int ch = 0; ch < nch; ++ch) {
        int buf = ch & 1;
        if (ch + 1 < nch) {
            int nb = buf ^ 1, k0 = (ch + 1) * 32;
            stage_cp(tile(nb, 0), Ahi, lda, k0, t);
            stage_cp(tile(nb, 1), Alo, lda, k0, t);
            stage_cp(tile(nb, 2), Bhi, ldb, k0, t);
            stage_cp(tile(nb, 3), Blo, ldb, k0, t);
            CP_COMMIT();
            CP_WAIT1();
        } else {
            CP_WAIT0();
        }
        __syncthreads();
        for (int p = 0; p < npass; p++)
            mma_steps(tile(buf, (p & 2) ? 1 : 0), tile(buf, (p & 1) ? 3 : 2), wm, wn, g, tg, acc);
        __syncthreads();
    }
}
#define GEMM_DSMEM (8 * TILE_BYTES)

#define GEMM_PROLOG() \
    extern __shared__ char dsm[]; \
    int t = threadIdx.x, w = t >> 5, lane = t & 31; \
    int wm = (w & 1) * 64, wn = (w >> 1) * 32; \
    int g = lane >> 2, tg = lane & 3; \
    float acc[4][4][4] = {};

// ---------------- cvt: fp32 -> (hi, lo) bf16 ----------------------------------
__global__ __launch_bounds__(256) void cvt_x(const float* __restrict__ s) {
    int i = blockIdx.x * 256 + threadIdx.x;
    if (i < BB * SS * DD) {
        float v = s[i];
        __nv_bfloat16 h = __float2bfloat16(v);
        g_xhi[i] = h;
        g_xlo[i] = __float2bfloat16(v - __bfloat162float(h));
    }
}
__global__ __launch_bounds__(256) void cvt_w3(const float* __restrict__ s) {
    int i = blockIdx.x * 256 + threadIdx.x;
    if (i < 3 * DD * DD) {
        float v = s[i];
        __nv_bfloat16 h = __float2bfloat16(v);
        g_w3hi[i] = h;
        g_w3lo[i] = __float2bfloat16(v - __bfloat162float(h));
    }
}
__global__ __launch_bounds__(256) void cvt_w1(const float* __restrict__ s) {
    int i = blockIdx.x * 256 + threadIdx.x;
    if (i < DD * DD) {
        float v = s[i];
        __nv_bfloat16 h = __float2bfloat16(v);
        g_w1hi[i] = h;
        g_w1lo[i] = __float2bfloat16(v - __bfloat162float(h));
    }
}

// ---------------- K1: QKV GEMM ------------------------------------------------
__global__ __launch_bounds__(256) void qkv_mma(const float* __restrict__ bias) {
    GEMM_PROLOG();
    int bx = blockIdx.x, by = blockIdx.y;
    gemm_db(g_xhi + (size_t)by * 128 * DD, g_xlo + (size_t)by * 128 * DD, DD,
            g_w3hi + (size_t)bx * 128 * DD, g_w3lo + (size_t)bx * 128 * DD, DD,
            DD, 3, dsm, t, wm, wn, g, tg, acc);
#pragma unroll
    for (int mt = 0; mt < 4; mt++)
#pragma unroll
        for (int nt = 0; nt < 4; nt++) {
            float* c = acc[mt][nt];
#pragma unroll
            for (int half = 0; half < 2; half++) {
                int m = by * 128 + wm + mt * 16 + g + half * 8;
                int n = bx * 128 + wn + nt * 8 + tg * 2;
                float v0 = c[half * 2] + bias[n];
                float v1 = c[half * 2 + 1] + bias[n + 1];
                int which = n >> 10, h = (n >> 6) & 15, d = n & 63;
                int b = m >> 11, s = m & (SS - 1);
                int bh = b * HH + h;
                if (which == 0) {
                    size_t di = ((size_t)bh * SS + s) * HD + d;
                    uint32_t hi, lo;
                    split2(v0 * 0.125f, v1 * 0.125f, hi, lo);
                    *(uint32_t*)&g_qhi[di] = hi;
                    *(uint32_t*)&g_qlo[di] = lo;
                } else if (which == 1) {
                    size_t di = ((size_t)bh * SS + s) * HD + d;
                    uint32_t hi, lo;
                    split2(v0, v1, hi, lo);
                    *(uint32_t*)&g_khi[di] = hi;
                    *(uint32_t*)&g_klo[di] = lo;
                } else {
                    size_t di = ((size_t)bh * HD + d) * SS + s;
                    __nv_bfloat16 h0 = __float2bfloat16(v0), h1 = __float2bfloat16(v1);
                    g_vthi[di] = h0;
                    g_vtlo[di] = __float2bfloat16(v0 - __bfloat162float(h0));
                    g_vthi[di + SS] = h1;
                    g_vtlo[di + SS] = __float2bfloat16(v1 - __bfloat162float(h1));
                }
            }
        }
}

// ---------------- K2: stats ---------------------------------------------------
__global__ __launch_bounds__(256) void stats_kernel(const float* __restrict__ x) {
    int bh = blockIdx.x;
    int b = bh / HH, h = bh % HH;
    int t = threadIdx.x;
    __shared__ float part[256];
    __shared__ float cent[64];
    int d = t & 63, grp = t >> 6;
    float acc = 0.f;
    for (int s = grp; s < SS; s += 4)
        acc += x[((size_t)(b * SS + s)) * DD + h * HD + d];
    part[t] = acc;
    __syncthreads();
    if (t < 64) cent[t] = (part[t] + part[t + 64] + part[t + 128] + part[t + 192]) * (1.0f / SS);
    __syncthreads();
    float lmax = 0.f;
    for (int s = t; s < SS; s += 256) {
        const float* xp = x + (size_t)(b * SS + s) * DD + h * HD;
        float sq = 0.f, dc2 = 0.f;
#pragma unroll
        for (int dd = 0; dd < HD; ++dd) {
            float v = xp[dd];
            sq += v * v;
            float wv = v - cent[dd];
            dc2 += wv * wv;
        }
        g_sq[bh * SS + s] = sq;
        float dc = sqrtf(dc2);
        g_d2c[bh * SS + s] = dc;
        lmax = fmaxf(lmax, dc);
    }
    __syncthreads();
    part[t] = lmax;
    __syncthreads();
    for (int off = 128; off > 0; off >>= 1) {
        if (t < off) part[t] = fmaxf(part[t], part[t + off]);
        __syncthreads();
    }
    if (t == 0) {
        g_d2cmax[bh] = part[0];
        g_kdmax[bh] = 0.f;
    }
}

// ---------------- K3+K4 fused: pairwise dist + 10th-smallest ------------------
// smem layout (dynamic):
//   A hi/lo:  2 x 17408  @ 0
//   B bufs:   4 x 17408  @ 34816   ((buf*2+idx)*17408)
//   sD:       128 x 129 f32 @ 104448
#define DT_B 34816
#define DT_D 104448
#define DIST_SMEM (104448 + 128 * 129 * 4)
__global__ __launch_bounds__(256) void distkth_mma() {
    extern __shared__ char dsm[];
    __nv_bfloat16* aT[2] = {(__nv_bfloat16*)dsm, (__nv_bfloat16*)(dsm + 17408)};
    float* sD = (float*)(dsm + DT_D);
    int t = threadIdx.x, w = t >> 5, lane = t & 31;
    int wm = (w & 1) * 64, wn = (w >> 1) * 32;
    int g = lane >> 2, tg = lane & 3;
    int bh = blockIdx.y;
    int m0 = blockIdx.x * 128;
    const __nv_bfloat16* xh = g_xhi + (size_t)(bh >> 4) * SS * DD + (bh & 15) * HD;
    const __nv_bfloat16* xl = g_xlo + (size_t)(bh >> 4) * SS * DD + (bh & 15) * HD;

    // stage A (rows m0..m0+127, K=64) once
#pragma unroll
    for (int i = 0; i < 8; i++) {
        int lin = t + i * 256;
        int r = lin >> 4, hh = lin & 15;
        *(uint2*)&aT[0][r * SA2 + hh * 4] = *(const uint2*)&xh[(size_t)(m0 + r) * DD + hh * 4];
        *(uint2*)&aT[1][r * SA2 + hh * 4] = *(const uint2*)&xl[(size_t)(m0 + r) * DD + hh * 4];
    }
    auto bT = [&](int buf, int idx) {
        return (__nv_bfloat16*)(dsm + DT_B + (buf * 2 + idx) * 17408);
    };
    // prefetch B chunk 0
    stage_cp64(bT(0, 0), xh, DD, t);
    stage_cp64(bT(0, 1), xl, DD, t);
    CP_COMMIT();

    float ls[10];
#pragma unroll
    for (int q = 0; q < 10; q++) ls[q] = 1e30f;
    int row_l = t >> 1;       // scan row (0..127)
    int c0 = (t & 1) * 64;    // scan half

    for (int ct = 0; ct < 16; ++ct) {
        int buf = ct & 1;
        if (ct + 1 < 16) {
            stage_cp64(bT(buf ^ 1, 0), xh + (size_t)(ct + 1) * 128 * DD, DD, t);
            stage_cp64(bT(buf ^ 1, 1), xl + (size_t)(ct + 1) * 128 * DD, DD, t);
            CP_COMMIT();
            CP_WAIT1();
        } else {
            CP_WAIT0();
        }
        __syncthreads();
        float acc[4][4][4];
#pragma unroll
        for (int a = 0; a < 4; a++)
#pragma unroll
            for (int b2 = 0; b2 < 4; b2++)
#pragma unroll
                for (int c2 = 0; c2 < 4; c2++) acc[a][b2][c2] = 0.f;
        // 4 passes: hh, hl, lh, ll
        mma_steps64(aT[0], bT(buf, 0), wm, wn, g, tg, acc);
        mma_steps64(aT[0], bT(buf, 1), wm, wn, g, tg, acc);
        mma_steps64(aT[1], bT(buf, 0), wm, wn, g, tg, acc);
        mma_steps64(aT[1], bT(buf, 1), wm, wn, g, tg, acc);
        // write (sqj - 2*dot) to sD
#pragma unroll
        for (int mt = 0; mt < 4; mt++)
#pragma unroll
            for (int nt = 0; nt < 4; nt++) {
                float* c = acc[mt][nt];
#pragma unroll
                for (int half = 0; half < 2; half++) {
                    int ml = wm + mt * 16 + g + half * 8;
                    int nl = wn + nt * 8 + tg * 2;
                    float2 sqj = *(const float2*)&g_sq[bh * SS + ct * 128 + nl];
                    sD[ml * 129 + nl] = sqj.x - 2.f * c[half * 2];
                    sD[ml * 129 + nl + 1] = sqj.y - 2.f * c[half * 2 + 1];
                }
            }
        __syncthreads();
        // scan: each thread scans 64 values of its row into register top-10
        const float* rp = &sD[row_l * 129 + c0];
#pragma unroll 8
        for (int i = 0; i < 64; ++i) {
            float v = rp[i];
            if (v < ls[9]) {
                ls[9] = v;
#pragma unroll
                for (int q = 9; q > 0; --q) {
                    if (ls[q] < ls[q - 1]) { float tm = ls[q]; ls[q] = ls[q - 1]; ls[q - 1] = tm; }
                }
            }
        }
        __syncthreads();
    }
    // merge the two half-row top-10s via sD
#pragma unroll
    for (int q = 0; q < 10; q++) sD[row_l * 129 + (t & 1) * 10 + q] = ls[q];
    __syncthreads();
    if ((t & 1) == 0) {
        const float* a = &sD[row_l * 129];
        const float* b = a + 10;
        int ia = 0, ib = 0;
        float kth = 0.f;
#pragma unroll
        for (int it = 0; it < 10; ++it)
            kth = (a[ia] <= b[ib]) ? a[ia++] : b[ib++];
        int m = m0 + row_l;
        float kd = sqrtf(fmaxf(g_sq[bh * SS + m] + kth, 0.f));
        g_kd[bh * SS + m] = kd;
        atomicMax((int*)&g_kdmax[bh], __float_as_int(kd));
    }
}

// ---------------- K5: tls -----------------------------------------------------
__global__ __launch_bounds__(256) void tls_kernel() {
    int bh = blockIdx.x;
    int t = threadIdx.x;
    float dinv = 1.0f / (g_d2cmax[bh] + 1e-8f);
    float kinv = 1.0f / (g_kdmax[bh] + 1e-8f);
    for (int s = t; s < SS; s += 256) {
        float life = g_d2c[bh * SS + s] * dinv;
        float mmd = g_kd[bh * SS + s] * kinv;
        g_tls[bh * SS + s] = 0.7f * life + 0.3f * mmd;
    }
}

// ---------------- K6: bitonic sort + mark -------------------------------------
__global__ __launch_bounds__(1024) void sort_mark_kernel() {
    __shared__ float a[SS];
    int t = threadIdx.x;
    int bh = blockIdx.x;
    a[t] = g_tls[bh * SS + t];
    a[t + 1024] = g_tls[bh * SS + t + 1024];
    __syncthreads();
    for (int k = 2; k <= SS; k <<= 1) {
        for (int j = k >> 1; j > 0; j >>= 1) {
#pragma unroll
            for (int half = 0; half < 2; ++half) {
                int i = t + half * 1024;
                int ixj = i ^ j;
                if (ixj > i) {
                    bool up = ((i & k) == 0);
                    float xi = a[i], xj = a[ixj];
                    if (up ? (xi > xj) : (xi < xj)) { a[i] = xj; a[ixj] = xi; }
                }
            }
            __syncthreads();
        }
    }
    float thresh = a[SS - NKEEP];
    __syncthreads();
#pragma unroll
    for (int half = 0; half < 2; ++half) {
        int s = t + half * 1024;
        g_mark[bh * SS + s] = (g_tls[bh * SS + s] >= thresh) ? 1 : 0;
    }
}

// ---------------- K7: score GEMM ----------------------------------------------
__global__ __launch_bounds__(256) void score_mma(float* __restrict__ attn) {
    GEMM_PROLOG();
    int bx = blockIdx.x, by = blockIdx.y, bh = blockIdx.z;
    size_t qo = ((size_t)bh * SS + by * 128) * HD;
    size_t ko = ((size_t)bh * SS + bx * 128) * HD;
    gemm_db(g_qhi + qo, g_qlo + qo, HD, g_khi + ko, g_klo + ko, HD, HD, 3,
            dsm, t, wm, wn, g, tg, acc);
    float* abase = attn + (size_t)bh * SS * SS;
#pragma unroll
    for (int mt = 0; mt < 4; mt++)
#pragma unroll
        for (int nt = 0; nt < 4; nt++) {
            float* c = acc[mt][nt];
#pragma unroll
            for (int half = 0; half < 2; half++) {
                int m = by * 128 + wm + mt * 16 + g + half * 8;
                int n = bx * 128 + wn + nt * 8 + tg * 2;
                float2 o;
                o.x = c[half * 2];
                o.y = c[half * 2 + 1];
                *(float2*)&abase[(size_t)m * SS + n] = o;
            }
        }
}

// ---------------- K8: masked softmax ------------------------------------------
__global__ __launch_bounds__(256) void softmax_kernel(float* __restrict__ attn) {
    extern __shared__ float smemf[];
    float* rows = smemf;
    unsigned char* mk = (unsigned char*)(rows + 8 * SS);
    int bh = blockIdx.y;
    int t = threadIdx.x, w = t >> 5, lane = t & 31;
    int i = blockIdx.x * 8 + w;
    for (int j = t; j < SS; j += 256) mk[j] = (unsigned char)g_mark[bh * SS + j];
    float* gp = attn + ((size_t)bh * SS + i) * SS;
    float* rb = rows + w * SS;
    for (int it = 0; it < 64; ++it) rb[lane + it * 32] = gp[lane + it * 32];
    __syncthreads();
    float m = -1e30f;
    for (int it = 0; it < 64; ++it) {
        int j = lane + it * 32;
        int rel = j - i;
        bool ms = (rel >= -W2 && rel <= W2) || mk[j];
        if (ms) m = fmaxf(m, rb[j]);
    }
#pragma unroll
    for (int off = 16; off; off >>= 1) m = fmaxf(m, __shfl_xor_sync(0xffffffffu, m, off));
    float sum = 0.f;
    for (int it = 0; it < 64; ++it) {
        int j = lane + it * 32;
        int rel = j - i;
        bool ms = (rel >= -W2 && rel <= W2) || mk[j];
        if (ms) sum += __expf(rb[j] - m);
    }
#pragma unroll
    for (int off = 16; off; off >>= 1) sum += __shfl_xor_sync(0xffffffffu, sum, off);
    float inv = 1.0f / sum;
    for (int it = 0; it < 64; ++it) {
        int j = lane + it * 32;
        int rel = j - i;
        bool ms = (rel >= -W2 && rel <= W2) || mk[j];
        gp[j] = ms ? __expf(rb[j] - m) * inv : 0.f;
    }
}

// ---------------- K9: AV GEMM -------------------------------------------------
__global__ __launch_bounds__(256) void av_mma(const float* __restrict__ attn) {
    __shared__ __nv_bfloat16 sAh[128 * SA], sAl[128 * SA];
    __shared__ __nv_bfloat16 sVh[64 * SA], sVl[64 * SA];
    int t = threadIdx.x, w = t >> 5, lane = t & 31;
    int wm = (w & 1) * 64, wn = (w >> 1) * 16;
    int g = lane >> 2, tg = lane & 3;
    int bx = blockIdx.x, bh = blockIdx.y;
    const float* Ap = attn + ((size_t)bh * SS + bx * 128) * SS;
    const __nv_bfloat16* Vh = g_vthi + (size_t)bh * HD * SS;
    const __nv_bfloat16* Vl = g_vtlo + (size_t)bh * HD * SS;
    float acc[4][2][4] = {};
    for (int k0 = 0; k0 < SS; k0 += 32) {
        __syncthreads();
        stage_f32_split(sAh, sAl, Ap, SS, k0, t);
        stage_bf(sVh, Vh, SS, k0, t, 2);
        stage_bf(sVl, Vl, SS, k0, t, 2);
        __syncthreads();
        for (int p = 0; p < 3; p++) {
            const __nv_bfloat16* As = (p & 2) ? sAl : sAh;
            const __nv_bfloat16* Bs = (p & 1) ? sVl : sVh;
#pragma unroll
            for (int s = 0; s < 2; s++) {
                int kk = s * 16;
                uint32_t afr[4][4];
#pragma unroll
                for (int mt = 0; mt < 4; mt++) {
                    int r0 = (wm + mt * 16 + g) * SA + kk + tg * 2;
                    afr[mt][0] = *(const uint32_t*)&As[r0];
                    afr[mt][1] = *(const uint32_t*)&As[r0 + 8 * SA];
                    afr[mt][2] = *(const uint32_t*)&As[r0 + 8];
                    afr[mt][3] = *(const uint32_t*)&As[r0 + 8 * SA + 8];
                }
#pragma unroll
                for (int nt = 0; nt < 2; nt++) {
                    int rb = (wn + nt * 8 + g) * SA + kk + tg * 2;
                    uint32_t b0 = *(const uint32_t*)&Bs[rb];
                    uint32_t b1 = *(const uint32_t*)&Bs[rb + 8];
#pragma unroll
                    for (int mt = 0; mt < 4; mt++)
                        mma16816(acc[mt][nt], afr[mt][0], afr[mt][1], afr[mt][2], afr[mt][3], b0, b1);
                }
            }
        }
    }
    int b = bh >> 4, h = bh & 15;
#pragma unroll
    for (int mt = 0; mt < 4; mt++)
#pragma unroll
        for (int nt = 0; nt < 2; nt++) {
            float* c = acc[mt][nt];
#pragma unroll
            for (int half = 0; half < 2; half++) {
                int s = bx * 128 + wm + mt * 16 + g + half * 8;
                int d = wn + nt * 8 + tg * 2;
                size_t di = ((size_t)(b * SS + s)) * DD + h * 64 + d;
                uint32_t hi, lo;
                split2(c[half * 2], c[half * 2 + 1], hi, lo);
                *(uint32_t*)&g_ohi[di] = hi;
                *(uint32_t*)&g_olo[di] = lo;
            }
        }
}

// ---------------- K10: output projection --------------------------------------
__global__ __launch_bounds__(256) void proj_mma(const float* __restrict__ bias,
                                                float* __restrict__ out) {
    GEMM_PROLOG();
    int bx = blockIdx.x, by = blockIdx.y;
    gemm_db(g_ohi + (size_t)by * 128 * DD, g_olo + (size_t)by * 128 * DD, DD,
            g_w1hi + (size_t)bx * 128 * DD, g_w1lo + (size_t)bx * 128 * DD, DD,
            DD, 3, dsm, t, wm, wn, g, tg, acc);
#pragma unroll
    for (int mt = 0; mt < 4; mt++)
#pragma unroll
        for (int nt = 0; nt < 4; nt++) {
            float* c = acc[mt][nt];
#pragma unroll
            for (int half = 0; half < 2; half++) {
                int m = by * 128 + wm + mt * 16 + g + half * 8;
                int n = bx * 128 + wn + nt * 8 + tg * 2;
                float2 o;
                o.x = c[half * 2] + bias[n];
                o.y = c[half * 2 + 1] + bias[n + 1];
                *(float2*)&out[(size_t)m * DD + n] = o;
            }
        }
}

// ---------------- launch ------------------------------------------------------
extern "C" void kernel_launch(void* const* d_in, const int* in_sizes, int n_in,
                              void* d_out, int out_size) {
    const float* x = (const float*)d_in[0];
    const float* qkv_w = (const float*)d_in[1];
    const float* qkv_b = (const float*)d_in[2];
    const float* out_w = (const float*)d_in[3];
    const float* out_b = (const float*)d_in[4];
    float* out = (float*)d_out;
    float* attn = out + (size_t)BB * SS * DD;

    const int SM_SMEM = 8 * SS * 4 + SS;
    cudaFuncSetAttribute(softmax_kernel, cudaFuncAttributeMaxDynamicSharedMemorySize, SM_SMEM);
    cudaFuncSetAttribute(qkv_mma, cudaFuncAttributeMaxDynamicSharedMemorySize, GEMM_DSMEM);
    cudaFuncSetAttribute(score_mma, cudaFuncAttributeMaxDynamicSharedMemorySize, GEMM_DSMEM);
    cudaFuncSetAttribute(proj_mma, cudaFuncAttributeMaxDynamicSharedMemorySize, GEMM_DSMEM);
    cudaFuncSetAttribute(distkth_mma, cudaFuncAttributeMaxDynamicSharedMemorySize, DIST_SMEM);

    cvt_x<<<(BB * SS * DD + 255) / 256, 256>>>(x);
    cvt_w3<<<(3 * DD * DD + 255) / 256, 256>>>(qkv_w);
    cvt_w1<<<(DD * DD + 255) / 256, 256>>>(out_w);

    qkv_mma<<<dim3(24, 32), 256, GEMM_DSMEM>>>(qkv_b);
    stats_kernel<<<BH, 256>>>(x);
    distkth_mma<<<dim3(16, BH), 256, DIST_SMEM>>>();
    tls_kernel<<<BH, 256>>>();
    sort_mark_kernel<<<BH, 1024>>>();
    score_mma<<<dim3(16, 16, BH), 256, GEMM_DSMEM>>>(attn);
    softmax_kernel<<<dim3(SS / 8, BH), 256, SM_SMEM>>>(attn);
    av_mma<<<dim3(16, BH), 256>>>(attn);
    proj_mma<<<dim3(8, 32), 256, GEMM_DSMEM>>>(out_b, out);
}

// round 7
// speedup vs baseline: 4.8648x; 1.1524x over previous
#include <cuda_runtime.h>
#include <cuda_bf16.h>
#include <math.h>
#include <stdint.h>

#define BB 2
#define SS 2048
#define DD 1024
#define HH 16
#define HD 64
#define BH (BB*HH)
#define NKEEP 675
#define W2 64
#define SA 40   // smem row stride (bf16), 32-wide K chunks: conflict-free (r*20+tg)
#define SA2 72  // smem row stride (bf16), 64-wide K chunks: conflict-free (r*4+tg)

// ---------------- scratch -----------------------------------------------------
__device__ float g_sq[BH*SS];
__device__ float g_d2c[BH*SS];
__device__ float g_d2cmax[BH];
__device__ float g_kd[BH*SS];
__device__ float g_kdmax[BH];
__device__ float g_tls[BH*SS];
__device__ int   g_mark[BH*SS];

__device__ __align__(256) __nv_bfloat16 g_xhi[BB*SS*DD];
__device__ __align__(256) __nv_bfloat16 g_xlo[BB*SS*DD];
__device__ __align__(256) __nv_bfloat16 g_w3hi[3*DD*DD];
__device__ __align__(256) __nv_bfloat16 g_w3lo[3*DD*DD];
__device__ __align__(256) __nv_bfloat16 g_w1hi[DD*DD];
__device__ __align__(256) __nv_bfloat16 g_w1lo[DD*DD];
__device__ __align__(256) __nv_bfloat16 g_qhi[BH*SS*HD];
__device__ __align__(256) __nv_bfloat16 g_qlo[BH*SS*HD];
__device__ __align__(256) __nv_bfloat16 g_khi[BH*SS*HD];
__device__ __align__(256) __nv_bfloat16 g_klo[BH*SS*HD];
__device__ __align__(256) __nv_bfloat16 g_vthi[BH*HD*SS];  // V^T: [bh][d][s]
__device__ __align__(256) __nv_bfloat16 g_vtlo[BH*HD*SS];
__device__ __align__(256) __nv_bfloat16 g_ohi[BB*SS*DD];
__device__ __align__(256) __nv_bfloat16 g_olo[BB*SS*DD];

// ---------------- helpers -----------------------------------------------------
__device__ __forceinline__ uint32_t s2u(const void* p) {
    uint32_t a;
    asm("{ .reg .u64 t; cvta.to.shared.u64 t, %1; cvt.u32.u64 %0, t; }" : "=r"(a) : "l"(p));
    return a;
}
__device__ __forceinline__ void mma16816(float* c, const uint32_t* a, const uint32_t* b) {
    asm volatile(
        "mma.sync.aligned.m16n8k16.row.col.f32.bf16.bf16.f32 "
        "{%0,%1,%2,%3}, {%4,%5,%6,%7}, {%8,%9}, {%0,%1,%2,%3};"
        : "+f"(c[0]), "+f"(c[1]), "+f"(c[2]), "+f"(c[3])
        : "r"(a[0]), "r"(a[1]), "r"(a[2]), "r"(a[3]), "r"(b[0]), "r"(b[1]));
}
__device__ __forceinline__ void split2(float x, float y, uint32_t& hi, uint32_t& lo) {
    __nv_bfloat16 hx = __float2bfloat16(x), hy = __float2bfloat16(y);
    __nv_bfloat162 h, l;
    h.x = hx; h.y = hy;
    l.x = __float2bfloat16(x - __bfloat162float(hx));
    l.y = __float2bfloat16(y - __bfloat162float(hy));
    hi = *(uint32_t*)&h;
    lo = *(uint32_t*)&l;
}
__device__ __forceinline__ void cp8(__nv_bfloat16* dst, const __nv_bfloat16* src) {
    uint32_t d = s2u(dst);
    asm volatile("cp.async.ca.shared.global [%0], [%1], 8;" :: "r"(d), "l"(src) : "memory");
}
#define CP_COMMIT() asm volatile("cp.async.commit_group;" ::: "memory")
#define CP_WAIT1() asm volatile("cp.async.wait_group 1;" ::: "memory")
#define CP_WAIT0() asm volatile("cp.async.wait_group 0;" ::: "memory")

// cp.async stage of a [128 x 32] bf16 tile -> smem [128][SA]
__device__ __forceinline__ void stage_cp(__nv_bfloat16* dst, const __nv_bfloat16* src,
                                         int ld, int k0, int t) {
#pragma unroll
    for (int i = 0; i < 4; i++) {
        int lin = t + i * 256;
        int r = lin >> 3, h = lin & 7;
        cp8(&dst[r * SA + h * 4], &src[(size_t)r * ld + k0 + h * 4]);
    }
}
// cp.async stage of a [128 x 64] bf16 tile -> smem [128][SA2]
__device__ __forceinline__ void stage_cp64(__nv_bfloat16* dst, const __nv_bfloat16* src,
                                           int ld, int t) {
#pragma unroll
    for (int i = 0; i < 8; i++) {
        int lin = t + i * 256;
        int r = lin >> 4, h = lin & 15;
        cp8(&dst[r * SA2 + h * 4], &src[(size_t)r * ld + h * 4]);
    }
}

// ---- fused-pass MMA over one K chunk: loads frags once, issues all passes ----
// STR: smem stride; NSTEP: k16 steps per chunk; NPASS: 3 (hh,hl,lh) or 4 (+ll)
template<int STR, int NSTEP, int NPASS>
__device__ __forceinline__ void mma_chunk(const __nv_bfloat16* Ah, const __nv_bfloat16* Al,
                                          const __nv_bfloat16* Bh, const __nv_bfloat16* Bl,
                                          int wm, int wn, int g, int tg, float (*acc)[4][4]) {
#pragma unroll
    for (int s = 0; s < NSTEP; s++) {
        int kk = s * 16;
        uint32_t ah[4][4], al[4][4], bh[4][2], bl[4][2];
#pragma unroll
        for (int mt = 0; mt < 4; mt++) {
            int r0 = (wm + mt * 16 + g) * STR + kk + tg * 2;
            ah[mt][0] = *(const uint32_t*)&Ah[r0];
            ah[mt][1] = *(const uint32_t*)&Ah[r0 + 8 * STR];
            ah[mt][2] = *(const uint32_t*)&Ah[r0 + 8];
            ah[mt][3] = *(const uint32_t*)&Ah[r0 + 8 * STR + 8];
            al[mt][0] = *(const uint32_t*)&Al[r0];
            al[mt][1] = *(const uint32_t*)&Al[r0 + 8 * STR];
            al[mt][2] = *(const uint32_t*)&Al[r0 + 8];
            al[mt][3] = *(const uint32_t*)&Al[r0 + 8 * STR + 8];
        }
#pragma unroll
        for (int nt = 0; nt < 4; nt++) {
            int rb = (wn + nt * 8 + g) * STR + kk + tg * 2;
            bh[nt][0] = *(const uint32_t*)&Bh[rb];
            bh[nt][1] = *(const uint32_t*)&Bh[rb + 8];
            bl[nt][0] = *(const uint32_t*)&Bl[rb];
            bl[nt][1] = *(const uint32_t*)&Bl[rb + 8];
        }
#pragma unroll
        for (int nt = 0; nt < 4; nt++)
#pragma unroll
            for (int mt = 0; mt < 4; mt++) {
                mma16816(acc[mt][nt], ah[mt], bh[nt]);
                mma16816(acc[mt][nt], ah[mt], bl[nt]);
                mma16816(acc[mt][nt], al[mt], bh[nt]);
                if (NPASS == 4) mma16816(acc[mt][nt], al[mt], bl[nt]);
            }
    }
}

// double-buffered mainloop (tiles: 0=Ahi 1=Alo 2=Bhi 3=Blo)
#define TILE_BYTES (128 * SA * 2)
__device__ __forceinline__ void gemm_db(const __nv_bfloat16* Ahi, const __nv_bfloat16* Alo, int lda,
                                        const __nv_bfloat16* Bhi, const __nv_bfloat16* Blo, int ldb,
                                        int K, char* dsm, int t, int wm, int wn,
                                        int g, int tg, float (*acc)[4][4]) {
    auto tile = [&](int buf, int idx) {
        return (__nv_bfloat16*)(dsm + (buf * 4 + idx) * TILE_BYTES);
    };
    stage_cp(tile(0, 0), Ahi, lda, 0, t);
    stage_cp(tile(0, 1), Alo, lda, 0, t);
    stage_cp(tile(0, 2), Bhi, ldb, 0, t);
    stage_cp(tile(0, 3), Blo, ldb, 0, t);
    CP_COMMIT();
    int nch = K / 32;
    for (int ch = 0; ch < nch; ++ch) {
        int buf = ch & 1;
        if (ch + 1 < nch) {
            int nb = buf ^ 1, k0 = (ch + 1) * 32;
            stage_cp(tile(nb, 0), Ahi, lda, k0, t);
            stage_cp(tile(nb, 1), Alo, lda, k0, t);
            stage_cp(tile(nb, 2), Bhi, ldb, k0, t);
            stage_cp(tile(nb, 3), Blo, ldb, k0, t);
            CP_COMMIT();
            CP_WAIT1();
        } else {
            CP_WAIT0();
        }
        __syncthreads();
        mma_chunk<SA, 2, 3>(tile(buf, 0), tile(buf, 1), tile(buf, 2), tile(buf, 3),
                            wm, wn, g, tg, acc);
        __syncthreads();
    }
}
#define GEMM_DSMEM (8 * TILE_BYTES)

#define GEMM_PROLOG() \
    extern __shared__ char dsm[]; \
    int t = threadIdx.x, w = t >> 5, lane = t & 31; \
    int wm = (w & 1) * 64, wn = (w >> 1) * 32; \
    int g = lane >> 2, tg = lane & 3; \
    float acc[4][4][4] = {};

// ---------------- cvt: fp32 -> (hi, lo) bf16 ----------------------------------
__global__ __launch_bounds__(256) void cvt_x(const float* __restrict__ s) {
    int i = blockIdx.x * 256 + threadIdx.x;
    if (i < BB * SS * DD) {
        float v = s[i];
        __nv_bfloat16 h = __float2bfloat16(v);
        g_xhi[i] = h;
        g_xlo[i] = __float2bfloat16(v - __bfloat162float(h));
    }
}
__global__ __launch_bounds__(256) void cvt_w3(const float* __restrict__ s) {
    int i = blockIdx.x * 256 + threadIdx.x;
    if (i < 3 * DD * DD) {
        float v = s[i];
        __nv_bfloat16 h = __float2bfloat16(v);
        g_w3hi[i] = h;
        g_w3lo[i] = __float2bfloat16(v - __bfloat162float(h));
    }
}
__global__ __launch_bounds__(256) void cvt_w1(const float* __restrict__ s) {
    int i = blockIdx.x * 256 + threadIdx.x;
    if (i < DD * DD) {
        float v = s[i];
        __nv_bfloat16 h = __float2bfloat16(v);
        g_w1hi[i] = h;
        g_w1lo[i] = __float2bfloat16(v - __bfloat162float(h));
    }
}

// ---------------- K1: QKV GEMM ------------------------------------------------
__global__ __launch_bounds__(256, 2) void qkv_mma(const float* __restrict__ bias) {
    GEMM_PROLOG();
    int bx = blockIdx.x, by = blockIdx.y;
    gemm_db(g_xhi + (size_t)by * 128 * DD, g_xlo + (size_t)by * 128 * DD, DD,
            g_w3hi + (size_t)bx * 128 * DD, g_w3lo + (size_t)bx * 128 * DD, DD,
            DD, dsm, t, wm, wn, g, tg, acc);
#pragma unroll
    for (int mt = 0; mt < 4; mt++)
#pragma unroll
        for (int nt = 0; nt < 4; nt++) {
            float* c = acc[mt][nt];
#pragma unroll
            for (int half = 0; half < 2; half++) {
                int m = by * 128 + wm + mt * 16 + g + half * 8;
                int n = bx * 128 + wn + nt * 8 + tg * 2;
                float v0 = c[half * 2] + bias[n];
                float v1 = c[half * 2 + 1] + bias[n + 1];
                int which = n >> 10, h = (n >> 6) & 15, d = n & 63;
                int b = m >> 11, s = m & (SS - 1);
                int bh = b * HH + h;
                if (which == 0) {
                    size_t di = ((size_t)bh * SS + s) * HD + d;
                    uint32_t hi, lo;
                    split2(v0 * 0.125f, v1 * 0.125f, hi, lo);
                    *(uint32_t*)&g_qhi[di] = hi;
                    *(uint32_t*)&g_qlo[di] = lo;
                } else if (which == 1) {
                    size_t di = ((size_t)bh * SS + s) * HD + d;
                    uint32_t hi, lo;
                    split2(v0, v1, hi, lo);
                    *(uint32_t*)&g_khi[di] = hi;
                    *(uint32_t*)&g_klo[di] = lo;
                } else {
                    size_t di = ((size_t)bh * HD + d) * SS + s;
                    __nv_bfloat16 h0 = __float2bfloat16(v0), h1 = __float2bfloat16(v1);
                    g_vthi[di] = h0;
                    g_vtlo[di] = __float2bfloat16(v0 - __bfloat162float(h0));
                    g_vthi[di + SS] = h1;
                    g_vtlo[di + SS] = __float2bfloat16(v1 - __bfloat162float(h1));
                }
            }
        }
}

// ---------------- K2: stats ---------------------------------------------------
__global__ __launch_bounds__(256) void stats_kernel(const float* __restrict__ x) {
    int bh = blockIdx.x;
    int b = bh / HH, h = bh % HH;
    int t = threadIdx.x;
    __shared__ float part[256];
    __shared__ float cent[64];
    int d = t & 63, grp = t >> 6;
    float acc = 0.f;
    for (int s = grp; s < SS; s += 4)
        acc += x[((size_t)(b * SS + s)) * DD + h * HD + d];
    part[t] = acc;
    __syncthreads();
    if (t < 64) cent[t] = (part[t] + part[t + 64] + part[t + 128] + part[t + 192]) * (1.0f / SS);
    __syncthreads();
    float lmax = 0.f;
    for (int s = t; s < SS; s += 256) {
        const float* xp = x + (size_t)(b * SS + s) * DD + h * HD;
        float sq = 0.f, dc2 = 0.f;
#pragma unroll
        for (int dd = 0; dd < HD; ++dd) {
            float v = xp[dd];
            sq += v * v;
            float wv = v - cent[dd];
            dc2 += wv * wv;
        }
        g_sq[bh * SS + s] = sq;
        float dc = sqrtf(dc2);
        g_d2c[bh * SS + s] = dc;
        lmax = fmaxf(lmax, dc);
    }
    __syncthreads();
    part[t] = lmax;
    __syncthreads();
    for (int off = 128; off > 0; off >>= 1) {
        if (t < off) part[t] = fmaxf(part[t], part[t + off]);
        __syncthreads();
    }
    if (t == 0) {
        g_d2cmax[bh] = part[0];
        g_kdmax[bh] = 0.f;
    }
}

// ---------------- K3+K4 fused: pairwise dist + 10th-smallest ------------------
#define TILE64 (128 * SA2 * 2)
#define DT_B (2 * TILE64)
#define DT_D (DT_B + 4 * TILE64)
#define DIST_SMEM (DT_D + 128 * 129 * 4)
__global__ __launch_bounds__(256) void distkth_mma() {
    extern __shared__ char dsm[];
    __nv_bfloat16* aT[2] = {(__nv_bfloat16*)dsm, (__nv_bfloat16*)(dsm + TILE64)};
    float* sD = (float*)(dsm + DT_D);
    int t = threadIdx.x, w = t >> 5, lane = t & 31;
    int wm = (w & 1) * 64, wn = (w >> 1) * 32;
    int g = lane >> 2, tg = lane & 3;
    int bh = blockIdx.y;
    int m0 = blockIdx.x * 128;
    const __nv_bfloat16* xh = g_xhi + (size_t)(bh >> 4) * SS * DD + (bh & 15) * HD;
    const __nv_bfloat16* xl = g_xlo + (size_t)(bh >> 4) * SS * DD + (bh & 15) * HD;

#pragma unroll
    for (int i = 0; i < 8; i++) {
        int lin = t + i * 256;
        int r = lin >> 4, hh = lin & 15;
        *(uint2*)&aT[0][r * SA2 + hh * 4] = *(const uint2*)&xh[(size_t)(m0 + r) * DD + hh * 4];
        *(uint2*)&aT[1][r * SA2 + hh * 4] = *(const uint2*)&xl[(size_t)(m0 + r) * DD + hh * 4];
    }
    auto bT = [&](int buf, int idx) {
        return (__nv_bfloat16*)(dsm + DT_B + (buf * 2 + idx) * TILE64);
    };
    stage_cp64(bT(0, 0), xh, DD, t);
    stage_cp64(bT(0, 1), xl, DD, t);
    CP_COMMIT();

    float ls[10];
#pragma unroll
    for (int q = 0; q < 10; q++) ls[q] = 1e30f;
    int row_l = t >> 1;
    int c0 = (t & 1) * 64;

    for (int ct = 0; ct < 16; ++ct) {
        int buf = ct & 1;
        if (ct + 1 < 16) {
            stage_cp64(bT(buf ^ 1, 0), xh + (size_t)(ct + 1) * 128 * DD, DD, t);
            stage_cp64(bT(buf ^ 1, 1), xl + (size_t)(ct + 1) * 128 * DD, DD, t);
            CP_COMMIT();
            CP_WAIT1();
        } else {
            CP_WAIT0();
        }
        __syncthreads();
        float acc[4][4][4];
#pragma unroll
        for (int a = 0; a < 4; a++)
#pragma unroll
            for (int b2 = 0; b2 < 4; b2++)
#pragma unroll
                for (int c2 = 0; c2 < 4; c2++) acc[a][b2][c2] = 0.f;
        mma_chunk<SA2, 4, 4>(aT[0], aT[1], bT(buf, 0), bT(buf, 1), wm, wn, g, tg, acc);
#pragma unroll
        for (int mt = 0; mt < 4; mt++)
#pragma unroll
            for (int nt = 0; nt < 4; nt++) {
                float* c = acc[mt][nt];
#pragma unroll
                for (int half = 0; half < 2; half++) {
                    int ml = wm + mt * 16 + g + half * 8;
                    int nl = wn + nt * 8 + tg * 2;
                    float2 sqj = *(const float2*)&g_sq[bh * SS + ct * 128 + nl];
                    sD[ml * 129 + nl] = sqj.x - 2.f * c[half * 2];
                    sD[ml * 129 + nl + 1] = sqj.y - 2.f * c[half * 2 + 1];
                }
            }
        __syncthreads();
        const float* rp = &sD[row_l * 129 + c0];
#pragma unroll 8
        for (int i = 0; i < 64; ++i) {
            float v = rp[i];
            if (v < ls[9]) {
                ls[9] = v;
#pragma unroll
                for (int q = 9; q > 0; --q) {
                    if (ls[q] < ls[q - 1]) { float tm = ls[q]; ls[q] = ls[q - 1]; ls[q - 1] = tm; }
                }
            }
        }
        __syncthreads();
    }
#pragma unroll
    for (int q = 0; q < 10; q++) sD[row_l * 129 + (t & 1) * 10 + q] = ls[q];
    __syncthreads();
    if ((t & 1) == 0) {
        const float* a = &sD[row_l * 129];
        const float* b = a + 10;
        int ia = 0, ib = 0;
        float kth = 0.f;
#pragma unroll
        for (int it = 0; it < 10; ++it)
            kth = (a[ia] <= b[ib]) ? a[ia++] : b[ib++];
        int m = m0 + row_l;
        float kd = sqrtf(fmaxf(g_sq[bh * SS + m] + kth, 0.f));
        g_kd[bh * SS + m] = kd;
        atomicMax((int*)&g_kdmax[bh], __float_as_int(kd));
    }
}

// ---------------- K5: tls -----------------------------------------------------
__global__ __launch_bounds__(256) void tls_kernel() {
    int bh = blockIdx.x;
    int t = threadIdx.x;
    float dinv = 1.0f / (g_d2cmax[bh] + 1e-8f);
    float kinv = 1.0f / (g_kdmax[bh] + 1e-8f);
    for (int s = t; s < SS; s += 256) {
        float life = g_d2c[bh * SS + s] * dinv;
        float mmd = g_kd[bh * SS + s] * kinv;
        g_tls[bh * SS + s] = 0.7f * life + 0.3f * mmd;
    }
}

// ---------------- K6: bitonic sort + mark -------------------------------------
__global__ __launch_bounds__(1024) void sort_mark_kernel() {
    __shared__ float a[SS];
    int t = threadIdx.x;
    int bh = blockIdx.x;
    a[t] = g_tls[bh * SS + t];
    a[t + 1024] = g_tls[bh * SS + t + 1024];
    __syncthreads();
    for (int k = 2; k <= SS; k <<= 1) {
        for (int j = k >> 1; j > 0; j >>= 1) {
#pragma unroll
            for (int half = 0; half < 2; ++half) {
                int i = t + half * 1024;
                int ixj = i ^ j;
                if (ixj > i) {
                    bool up = ((i & k) == 0);
                    float xi = a[i], xj = a[ixj];
                    if (up ? (xi > xj) : (xi < xj)) { a[i] = xj; a[ixj] = xi; }
                }
            }
            __syncthreads();
        }
    }
    float thresh = a[SS - NKEEP];
    __syncthreads();
#pragma unroll
    for (int half = 0; half < 2; ++half) {
        int s = t + half * 1024;
        g_mark[bh * SS + s] = (g_tls[bh * SS + s] >= thresh) ? 1 : 0;
    }
}

// ---------------- K7: score GEMM ----------------------------------------------
__global__ __launch_bounds__(256, 2) void score_mma(float* __restrict__ attn) {
    GEMM_PROLOG();
    int bx = blockIdx.x, by = blockIdx.y, bh = blockIdx.z;
    size_t qo = ((size_t)bh * SS + by * 128) * HD;
    size_t ko = ((size_t)bh * SS + bx * 128) * HD;
    gemm_db(g_qhi + qo, g_qlo + qo, HD, g_khi + ko, g_klo + ko, HD, HD,
            dsm, t, wm, wn, g, tg, acc);
    float* abase = attn + (size_t)bh * SS * SS;
#pragma unroll
    for (int mt = 0; mt < 4; mt++)
#pragma unroll
        for (int nt = 0; nt < 4; nt++) {
            float* c = acc[mt][nt];
#pragma unroll
            for (int half = 0; half < 2; half++) {
                int m = by * 128 + wm + mt * 16 + g + half * 8;
                int n = bx * 128 + wn + nt * 8 + tg * 2;
                float2 o;
                o.x = c[half * 2];
                o.y = c[half * 2 + 1];
                *(float2*)&abase[(size_t)m * SS + n] = o;
            }
        }
}

// ---------------- K8: masked softmax ------------------------------------------
__global__ __launch_bounds__(256) void softmax_kernel(float* __restrict__ attn) {
    extern __shared__ float smemf[];
    float* rows = smemf;
    unsigned char* mk = (unsigned char*)(rows + 8 * SS);
    int bh = blockIdx.y;
    int t = threadIdx.x, w = t >> 5, lane = t & 31;
    int i = blockIdx.x * 8 + w;
    for (int j = t; j < SS; j += 256) mk[j] = (unsigned char)g_mark[bh * SS + j];
    float* gp = attn + ((size_t)bh * SS + i) * SS;
    float* rb = rows + w * SS;
    for (int it = 0; it < 64; ++it) rb[lane + it * 32] = gp[lane + it * 32];
    __syncthreads();
    float m = -1e30f;
    for (int it = 0; it < 64; ++it) {
        int j = lane + it * 32;
        int rel = j - i;
        bool ms = (rel >= -W2 && rel <= W2) || mk[j];
        if (ms) m = fmaxf(m, rb[j]);
    }
#pragma unroll
    for (int off = 16; off; off >>= 1) m = fmaxf(m, __shfl_xor_sync(0xffffffffu, m, off));
    float sum = 0.f;
    for (int it = 0; it < 64; ++it) {
        int j = lane + it * 32;
        int rel = j - i;
        bool ms = (rel >= -W2 && rel <= W2) || mk[j];
        if (ms) sum += __expf(rb[j] - m);
    }
#pragma unroll
    for (int off = 16; off; off >>= 1) sum += __shfl_xor_sync(0xffffffffu, sum, off);
    float inv = 1.0f / sum;
    for (int it = 0; it < 64; ++it) {
        int j = lane + it * 32;
        int rel = j - i;
        bool ms = (rel >= -W2 && rel <= W2) || mk[j];
        gp[j] = ms ? __expf(rb[j] - m) * inv : 0.f;
    }
}

// ---------------- K9: AV GEMM (pipelined, fused passes) -----------------------
__global__ __launch_bounds__(256, 2) void av_mma(const float* __restrict__ attn) {
    __shared__ __nv_bfloat16 sAh[128 * SA], sAl[128 * SA];
    __shared__ __nv_bfloat16 sVh[2][64 * SA], sVl[2][64 * SA];
    int t = threadIdx.x, w = t >> 5, lane = t & 31;
    int wm = (w & 1) * 64, wn = (w >> 1) * 16;
    int g = lane >> 2, tg = lane & 3;
    int bx = blockIdx.x, bh = blockIdx.y;
    const float* Ap = attn + ((size_t)bh * SS + bx * 128) * SS;
    const __nv_bfloat16* Vh = g_vthi + (size_t)bh * HD * SS;
    const __nv_bfloat16* Vl = g_vtlo + (size_t)bh * HD * SS;

    // prologue: prefetch attn chunk 0 into regs, V chunk 0 via cp.async
    float2 pv[8];
#pragma unroll
    for (int i = 0; i < 8; i++) {
        int lin = t + i * 256;
        int r = lin >> 4, h = lin & 15;
        pv[i] = *(const float2*)&Ap[(size_t)r * SS + h * 2];
    }
#pragma unroll
    for (int i = 0; i < 2; i++) {
        int lin = t + i * 256;
        int r = lin >> 3, h = lin & 7;
        cp8(&sVh[0][r * SA + h * 4], &Vh[(size_t)r * SS + h * 4]);
        cp8(&sVl[0][r * SA + h * 4], &Vl[(size_t)r * SS + h * 4]);
    }
    CP_COMMIT();

    float acc[4][2][4] = {};
    for (int ch = 0; ch < SS / 32; ++ch) {
        int buf = ch & 1;
        __syncthreads();  // prior mma done: safe to overwrite sA / V buf^1
        // split staged attn regs -> bf16 hi/lo smem
#pragma unroll
        for (int i = 0; i < 8; i++) {
            int lin = t + i * 256;
            int r = lin >> 4, h = lin & 15;
            uint32_t hi, lo;
            split2(pv[i].x, pv[i].y, hi, lo);
            *(uint32_t*)&sAh[r * SA + h * 2] = hi;
            *(uint32_t*)&sAl[r * SA + h * 2] = lo;
        }
        if (ch + 1 < SS / 32) {
            int k0n = (ch + 1) * 32;
#pragma unroll
            for (int i = 0; i < 2; i++) {
                int lin = t + i * 256;
                int r = lin >> 3, h = lin & 7;
                cp8(&sVh[buf ^ 1][r * SA + h * 4], &Vh[(size_t)r * SS + k0n + h * 4]);
                cp8(&sVl[buf ^ 1][r * SA + h * 4], &Vl[(size_t)r * SS + k0n + h * 4]);
            }
            CP_COMMIT();
#pragma unroll
            for (int i = 0; i < 8; i++) {
                int lin = t + i * 256;
                int r = lin >> 4, h = lin & 15;
                pv[i] = *(const float2*)&Ap[(size_t)r * SS + k0n + h * 2];
            }
            CP_WAIT1();
        } else {
            CP_WAIT0();
        }
        __syncthreads();
        // fused 3-pass mma: A 64x32 tile/warp, V 16-wide (nt=2)
        const __nv_bfloat16* Bh2 = sVh[buf];
        const __nv_bfloat16* Bl2 = sVl[buf];
#pragma unroll
        for (int s = 0; s < 2; s++) {
            int kk = s * 16;
            uint32_t ah[4][4], al[4][4], bhf[2][2], blf[2][2];
#pragma unroll
            for (int mt = 0; mt < 4; mt++) {
                int r0 = (wm + mt * 16 + g) * SA + kk + tg * 2;
                ah[mt][0] = *(const uint32_t*)&sAh[r0];
                ah[mt][1] = *(const uint32_t*)&sAh[r0 + 8 * SA];
                ah[mt][2] = *(const uint32_t*)&sAh[r0 + 8];
                ah[mt][3] = *(const uint32_t*)&sAh[r0 + 8 * SA + 8];
                al[mt][0] = *(const uint32_t*)&sAl[r0];
                al[mt][1] = *(const uint32_t*)&sAl[r0 + 8 * SA];
                al[mt][2] = *(const uint32_t*)&sAl[r0 + 8];
                al[mt][3] = *(const uint32_t*)&sAl[r0 + 8 * SA + 8];
            }
#pragma unroll
            for (int nt = 0; nt < 2; nt++) {
                int rb = (wn + nt * 8 + g) * SA + kk + tg * 2;
                bhf[nt][0] = *(const uint32_t*)&Bh2[rb];
                bhf[nt][1] = *(const uint32_t*)&Bh2[rb + 8];
                blf[nt][0] = *(const uint32_t*)&Bl2[rb];
                blf[nt][1] = *(const uint32_t*)&Bl2[rb + 8];
            }
#pragma unroll
            for (int nt = 0; nt < 2; nt++)
#pragma unroll
                for (int mt = 0; mt < 4; mt++) {
                    mma16816(acc[mt][nt], ah[mt], bhf[nt]);
                    mma16816(acc[mt][nt], ah[mt], blf[nt]);
                    mma16816(acc[mt][nt], al[mt], bhf[nt]);
                }
        }
    }
    int b = bh >> 4, h = bh & 15;
#pragma unroll
    for (int mt = 0; mt < 4; mt++)
#pragma unroll
        for (int nt = 0; nt < 2; nt++) {
            float* c = acc[mt][nt];
#pragma unroll
            for (int half = 0; half < 2; half++) {
                int s = bx * 128 + wm + mt * 16 + g + half * 8;
                int d = wn + nt * 8 + tg * 2;
                size_t di = ((size_t)(b * SS + s)) * DD + h * 64 + d;
                uint32_t hi, lo;
                split2(c[half * 2], c[half * 2 + 1], hi, lo);
                *(uint32_t*)&g_ohi[di] = hi;
                *(uint32_t*)&g_olo[di] = lo;
            }
        }
}

// ---------------- K10: output projection --------------------------------------
__global__ __launch_bounds__(256, 2) void proj_mma(const float* __restrict__ bias,
                                                   float* __restrict__ out) {
    GEMM_PROLOG();
    int bx = blockIdx.x, by = blockIdx.y;
    gemm_db(g_ohi + (size_t)by * 128 * DD, g_olo + (size_t)by * 128 * DD, DD,
            g_w1hi + (size_t)bx * 128 * DD, g_w1lo + (size_t)bx * 128 * DD, DD,
            DD, dsm, t, wm, wn, g, tg, acc);
#pragma unroll
    for (int mt = 0; mt < 4; mt++)
#pragma unroll
        for (int nt = 0; nt < 4; nt++) {
            float* c = acc[mt][nt];
#pragma unroll
            for (int half = 0; half < 2; half++) {
                int m = by * 128 + wm + mt * 16 + g + half * 8;
                int n = bx * 128 + wn + nt * 8 + tg * 2;
                float2 o;
                o.x = c[half * 2] + bias[n];
                o.y = c[half * 2 + 1] + bias[n + 1];
                *(float2*)&out[(size_t)m * DD + n] = o;
            }
        }
}

// ---------------- launch ------------------------------------------------------
extern "C" void kernel_launch(void* const* d_in, const int* in_sizes, int n_in,
                              void* d_out, int out_size) {
    const float* x = (const float*)d_in[0];
    const float* qkv_w = (const float*)d_in[1];
    const float* qkv_b = (const float*)d_in[2];
    const float* out_w = (const float*)d_in[3];
    const float* out_b = (const float*)d_in[4];
    float* out = (float*)d_out;
    float* attn = out + (size_t)BB * SS * DD;

    const int SM_SMEM = 8 * SS * 4 + SS;
    cudaFuncSetAttribute(softmax_kernel, cudaFuncAttributeMaxDynamicSharedMemorySize, SM_SMEM);
    cudaFuncSetAttribute(qkv_mma, cudaFuncAttributeMaxDynamicSharedMemorySize, GEMM_DSMEM);
    cudaFuncSetAttribute(score_mma, cudaFuncAttributeMaxDynamicSharedMemorySize, GEMM_DSMEM);
    cudaFuncSetAttribute(proj_mma, cudaFuncAttributeMaxDynamicSharedMemorySize, GEMM_DSMEM);
    cudaFuncSetAttribute(distkth_mma, cudaFuncAttributeMaxDynamicSharedMemorySize, DIST_SMEM);

    cvt_x<<<(BB * SS * DD + 255) / 256, 256>>>(x);
    cvt_w3<<<(3 * DD * DD + 255) / 256, 256>>>(qkv_w);
    cvt_w1<<<(DD * DD + 255) / 256, 256>>>(out_w);

    qkv_mma<<<dim3(24, 32), 256, GEMM_DSMEM>>>(qkv_b);
    stats_kernel<<<BH, 256>>>(x);
    distkth_mma<<<dim3(16, BH), 256, DIST_SMEM>>>();
    tls_kernel<<<BH, 256>>>();
    sort_mark_kernel<<<BH, 1024>>>();
    score_mma<<<dim3(16, 16, BH), 256, GEMM_DSMEM>>>(attn);
    softmax_kernel<<<dim3(SS / 8, BH), 256, SM_SMEM>>>(attn);
    av_mma<<<dim3(16, BH), 256>>>(attn);
    proj_mma<<<dim3(8, 32), 256, GEMM_DSMEM>>>(out_b, out);
}

// round 8
// speedup vs baseline: 5.3320x; 1.0960x over previous
#include <cuda_runtime.h>
#include <cuda_bf16.h>
#include <math.h>
#include <stdint.h>

#define BB 2
#define SS 2048
#define DD 1024
#define HH 16
#define HD 64
#define BH (BB*HH)
#define NKEEP 675
#define W2 64
#define SA 40   // smem row stride (bf16), 32-wide K chunks
#define SA2 72  // smem row stride (bf16), 64-wide K chunks

// ---------------- scratch -----------------------------------------------------
__device__ float g_sq[BH*SS];
__device__ float g_d2c[BH*SS];
__device__ float g_d2cmax[BH];
__device__ float g_kd[BH*SS];
__device__ float g_kdmax[BH];
__device__ float g_tls[BH*SS];
__device__ int   g_mark[BH*SS];

__device__ __align__(256) __nv_bfloat16 g_xhi[BB*SS*DD];
__device__ __align__(256) __nv_bfloat16 g_xlo[BB*SS*DD];
__device__ __align__(256) __nv_bfloat16 g_w3hi[3*DD*DD];
__device__ __align__(256) __nv_bfloat16 g_w3lo[3*DD*DD];
__device__ __align__(256) __nv_bfloat16 g_w1hi[DD*DD];
__device__ __align__(256) __nv_bfloat16 g_w1lo[DD*DD];
__device__ __align__(256) __nv_bfloat16 g_qhi[BH*SS*HD];
__device__ __align__(256) __nv_bfloat16 g_qlo[BH*SS*HD];
__device__ __align__(256) __nv_bfloat16 g_khi[BH*SS*HD];
__device__ __align__(256) __nv_bfloat16 g_klo[BH*SS*HD];
__device__ __align__(256) __nv_bfloat16 g_vthi[BH*HD*SS];  // V^T: [bh][d][s]
__device__ __align__(256) __nv_bfloat16 g_vtlo[BH*HD*SS];
__device__ __align__(256) __nv_bfloat16 g_ohi[BB*SS*DD];
__device__ __align__(256) __nv_bfloat16 g_olo[BB*SS*DD];

// ---------------- helpers -----------------------------------------------------
__device__ __forceinline__ uint32_t s2u(const void* p) {
    uint32_t a;
    asm("{ .reg .u64 t; cvta.to.shared.u64 t, %1; cvt.u32.u64 %0, t; }" : "=r"(a) : "l"(p));
    return a;
}
__device__ __forceinline__ void mma16816(float* c, const uint32_t* a, const uint32_t* b) {
    asm volatile(
        "mma.sync.aligned.m16n8k16.row.col.f32.bf16.bf16.f32 "
        "{%0,%1,%2,%3}, {%4,%5,%6,%7}, {%8,%9}, {%0,%1,%2,%3};"
        : "+f"(c[0]), "+f"(c[1]), "+f"(c[2]), "+f"(c[3])
        : "r"(a[0]), "r"(a[1]), "r"(a[2]), "r"(a[3]), "r"(b[0]), "r"(b[1]));
}
__device__ __forceinline__ void split2(float x, float y, uint32_t& hi, uint32_t& lo) {
    __nv_bfloat16 hx = __float2bfloat16(x), hy = __float2bfloat16(y);
    __nv_bfloat162 h, l;
    h.x = hx; h.y = hy;
    l.x = __float2bfloat16(x - __bfloat162float(hx));
    l.y = __float2bfloat16(y - __bfloat162float(hy));
    hi = *(uint32_t*)&h;
    lo = *(uint32_t*)&l;
}
__device__ __forceinline__ void cp8(__nv_bfloat16* dst, const __nv_bfloat16* src) {
    uint32_t d = s2u(dst);
    asm volatile("cp.async.ca.shared.global [%0], [%1], 8;" :: "r"(d), "l"(src) : "memory");
}
#define CP_COMMIT() asm volatile("cp.async.commit_group;" ::: "memory")
#define CP_WAIT1() asm volatile("cp.async.wait_group 1;" ::: "memory")
#define CP_WAIT0() asm volatile("cp.async.wait_group 0;" ::: "memory")

// cp.async stage of a [128 x 32] bf16 tile -> smem [128][SA]
__device__ __forceinline__ void stage_cp(__nv_bfloat16* dst, const __nv_bfloat16* src,
                                         int ld, int k0, int t) {
#pragma unroll
    for (int i = 0; i < 4; i++) {
        int lin = t + i * 256;
        int r = lin >> 3, h = lin & 7;
        cp8(&dst[r * SA + h * 4], &src[(size_t)r * ld + k0 + h * 4]);
    }
}
// cp.async stage of a [128 x 64] bf16 tile -> smem [128][SA2]
__device__ __forceinline__ void stage_cp64(__nv_bfloat16* dst, const __nv_bfloat16* src,
                                           int ld, int t) {
#pragma unroll
    for (int i = 0; i < 8; i++) {
        int lin = t + i * 256;
        int r = lin >> 4, h = lin & 15;
        cp8(&dst[r * SA2 + h * 4], &src[(size_t)r * ld + h * 4]);
    }
}

// ---- fused-pass MMA over one K chunk: loads frags once, issues all passes ----
template<int STR, int NSTEP, int NPASS>
__device__ __forceinline__ void mma_chunk(const __nv_bfloat16* Ah, const __nv_bfloat16* Al,
                                          const __nv_bfloat16* Bh, const __nv_bfloat16* Bl,
                                          int wm, int wn, int g, int tg, float (*acc)[4][4]) {
#pragma unroll
    for (int s = 0; s < NSTEP; s++) {
        int kk = s * 16;
        uint32_t ah[4][4], al[4][4], bh[4][2], bl[4][2];
#pragma unroll
        for (int mt = 0; mt < 4; mt++) {
            int r0 = (wm + mt * 16 + g) * STR + kk + tg * 2;
            ah[mt][0] = *(const uint32_t*)&Ah[r0];
            ah[mt][1] = *(const uint32_t*)&Ah[r0 + 8 * STR];
            ah[mt][2] = *(const uint32_t*)&Ah[r0 + 8];
            ah[mt][3] = *(const uint32_t*)&Ah[r0 + 8 * STR + 8];
            al[mt][0] = *(const uint32_t*)&Al[r0];
            al[mt][1] = *(const uint32_t*)&Al[r0 + 8 * STR];
            al[mt][2] = *(const uint32_t*)&Al[r0 + 8];
            al[mt][3] = *(const uint32_t*)&Al[r0 + 8 * STR + 8];
        }
#pragma unroll
        for (int nt = 0; nt < 4; nt++) {
            int rb = (wn + nt * 8 + g) * STR + kk + tg * 2;
            bh[nt][0] = *(const uint32_t*)&Bh[rb];
            bh[nt][1] = *(const uint32_t*)&Bh[rb + 8];
            bl[nt][0] = *(const uint32_t*)&Bl[rb];
            bl[nt][1] = *(const uint32_t*)&Bl[rb + 8];
        }
#pragma unroll
        for (int nt = 0; nt < 4; nt++)
#pragma unroll
            for (int mt = 0; mt < 4; mt++) {
                mma16816(acc[mt][nt], ah[mt], bh[nt]);
                mma16816(acc[mt][nt], ah[mt], bl[nt]);
                mma16816(acc[mt][nt], al[mt], bh[nt]);
                if (NPASS == 4) mma16816(acc[mt][nt], al[mt], bl[nt]);
            }
    }
}

// double-buffered mainloop for K>=128 GEMMs (tiles: 0=Ahi 1=Alo 2=Bhi 3=Blo)
#define TILE_BYTES (128 * SA * 2)
__device__ __forceinline__ void gemm_db(const __nv_bfloat16* Ahi, const __nv_bfloat16* Alo, int lda,
                                        const __nv_bfloat16* Bhi, const __nv_bfloat16* Blo, int ldb,
                                        int K, char* dsm, int t, int wm, int wn,
                                        int g, int tg, float (*acc)[4][4]) {
    auto tile = [&](int buf, int idx) {
        return (__nv_bfloat16*)(dsm + (buf * 4 + idx) * TILE_BYTES);
    };
    stage_cp(tile(0, 0), Ahi, lda, 0, t);
    stage_cp(tile(0, 1), Alo, lda, 0, t);
    stage_cp(tile(0, 2), Bhi, ldb, 0, t);
    stage_cp(tile(0, 3), Blo, ldb, 0, t);
    CP_COMMIT();
    int nch = K / 32;
    for (int ch = 0; ch < nch; ++ch) {
        int buf = ch & 1;
        if (ch + 1 < nch) {
            int nb = buf ^ 1, k0 = (ch + 1) * 32;
            stage_cp(tile(nb, 0), Ahi, lda, k0, t);
            stage_cp(tile(nb, 1), Alo, lda, k0, t);
            stage_cp(tile(nb, 2), Bhi, ldb, k0, t);
            stage_cp(tile(nb, 3), Blo, ldb, k0, t);
            CP_COMMIT();
            CP_WAIT1();
        } else {
            CP_WAIT0();
        }
        __syncthreads();
        mma_chunk<SA, 2, 3>(tile(buf, 0), tile(buf, 1), tile(buf, 2), tile(buf, 3),
                            wm, wn, g, tg, acc);
        __syncthreads();
    }
}
#define GEMM_DSMEM (8 * TILE_BYTES)

#define GEMM_PROLOG() \
    extern __shared__ char dsm[]; \
    int t = threadIdx.x, w = t >> 5, lane = t & 31; \
    int wm = (w & 1) * 64, wn = (w >> 1) * 32; \
    int g = lane >> 2, tg = lane & 3; \
    float acc[4][4][4] = {};

// ---------------- cvt: fp32 -> (hi, lo) bf16 ----------------------------------
__global__ __launch_bounds__(256) void cvt_x(const float* __restrict__ s) {
    int i = blockIdx.x * 256 + threadIdx.x;
    if (i < BB * SS * DD) {
        float v = s[i];
        __nv_bfloat16 h = __float2bfloat16(v);
        g_xhi[i] = h;
        g_xlo[i] = __float2bfloat16(v - __bfloat162float(h));
    }
}
__global__ __launch_bounds__(256) void cvt_w3(const float* __restrict__ s) {
    int i = blockIdx.x * 256 + threadIdx.x;
    if (i < 3 * DD * DD) {
        float v = s[i];
        __nv_bfloat16 h = __float2bfloat16(v);
        g_w3hi[i] = h;
        g_w3lo[i] = __float2bfloat16(v - __bfloat162float(h));
    }
}
__global__ __launch_bounds__(256) void cvt_w1(const float* __restrict__ s) {
    int i = blockIdx.x * 256 + threadIdx.x;
    if (i < DD * DD) {
        float v = s[i];
        __nv_bfloat16 h = __float2bfloat16(v);
        g_w1hi[i] = h;
        g_w1lo[i] = __float2bfloat16(v - __bfloat162float(h));
    }
}

// ---------------- K1: QKV GEMM ------------------------------------------------
__global__ __launch_bounds__(256, 2) void qkv_mma(const float* __restrict__ bias) {
    GEMM_PROLOG();
    int bx = blockIdx.x, by = blockIdx.y;
    gemm_db(g_xhi + (size_t)by * 128 * DD, g_xlo + (size_t)by * 128 * DD, DD,
            g_w3hi + (size_t)bx * 128 * DD, g_w3lo + (size_t)bx * 128 * DD, DD,
            DD, dsm, t, wm, wn, g, tg, acc);
#pragma unroll
    for (int mt = 0; mt < 4; mt++)
#pragma unroll
        for (int nt = 0; nt < 4; nt++) {
            float* c = acc[mt][nt];
#pragma unroll
            for (int half = 0; half < 2; half++) {
                int m = by * 128 + wm + mt * 16 + g + half * 8;
                int n = bx * 128 + wn + nt * 8 + tg * 2;
                float v0 = c[half * 2] + bias[n];
                float v1 = c[half * 2 + 1] + bias[n + 1];
                int which = n >> 10, h = (n >> 6) & 15, d = n & 63;
                int b = m >> 11, s = m & (SS - 1);
                int bh = b * HH + h;
                if (which == 0) {
                    size_t di = ((size_t)bh * SS + s) * HD + d;
                    uint32_t hi, lo;
                    split2(v0 * 0.125f, v1 * 0.125f, hi, lo);
                    *(uint32_t*)&g_qhi[di] = hi;
                    *(uint32_t*)&g_qlo[di] = lo;
                } else if (which == 1) {
                    size_t di = ((size_t)bh * SS + s) * HD + d;
                    uint32_t hi, lo;
                    split2(v0, v1, hi, lo);
                    *(uint32_t*)&g_khi[di] = hi;
                    *(uint32_t*)&g_klo[di] = lo;
                } else {
                    size_t di = ((size_t)bh * HD + d) * SS + s;
                    __nv_bfloat16 h0 = __float2bfloat16(v0), h1 = __float2bfloat16(v1);
                    g_vthi[di] = h0;
                    g_vtlo[di] = __float2bfloat16(v0 - __bfloat162float(h0));
                    g_vthi[di + SS] = h1;
                    g_vtlo[di + SS] = __float2bfloat16(v1 - __bfloat162float(h1));
                }
            }
        }
}

// ---------------- K2: stats ---------------------------------------------------
__global__ __launch_bounds__(256) void stats_kernel(const float* __restrict__ x) {
    int bh = blockIdx.x;
    int b = bh / HH, h = bh % HH;
    int t = threadIdx.x;
    __shared__ float part[256];
    __shared__ float cent[64];
    int d = t & 63, grp = t >> 6;
    float acc = 0.f;
    for (int s = grp; s < SS; s += 4)
        acc += x[((size_t)(b * SS + s)) * DD + h * HD + d];
    part[t] = acc;
    __syncthreads();
    if (t < 64) cent[t] = (part[t] + part[t + 64] + part[t + 128] + part[t + 192]) * (1.0f / SS);
    __syncthreads();
    float lmax = 0.f;
    for (int s = t; s < SS; s += 256) {
        const float* xp = x + (size_t)(b * SS + s) * DD + h * HD;
        float sq = 0.f, dc2 = 0.f;
#pragma unroll
        for (int dd = 0; dd < HD; ++dd) {
            float v = xp[dd];
            sq += v * v;
            float wv = v - cent[dd];
            dc2 += wv * wv;
        }
        g_sq[bh * SS + s] = sq;
        float dc = sqrtf(dc2);
        g_d2c[bh * SS + s] = dc;
        lmax = fmaxf(lmax, dc);
    }
    __syncthreads();
    part[t] = lmax;
    __syncthreads();
    for (int off = 128; off > 0; off >>= 1) {
        if (t < off) part[t] = fmaxf(part[t], part[t + off]);
        __syncthreads();
    }
    if (t == 0) {
        g_d2cmax[bh] = part[0];
        g_kdmax[bh] = 0.f;
    }
}

// ---------------- K3+K4 fused: pairwise dist + 10th-smallest (occ 2) ----------
// smem: A hi/lo 2x18432, B hi/lo 2x18432, sD 128x66 f32 -> 107.3 KB total
#define T64 (128 * SA2 * 2)
#define DK_SD (4 * T64)
#define DIST_SMEM (DK_SD + 128 * 66 * 4)
__global__ __launch_bounds__(256, 2) void distkth_mma() {
    extern __shared__ char dsm[];
    __nv_bfloat16* aH = (__nv_bfloat16*)dsm;
    __nv_bfloat16* aL = (__nv_bfloat16*)(dsm + T64);
    __nv_bfloat16* bH = (__nv_bfloat16*)(dsm + 2 * T64);
    __nv_bfloat16* bL = (__nv_bfloat16*)(dsm + 3 * T64);
    float* sD = (float*)(dsm + DK_SD);
    int t = threadIdx.x, w = t >> 5, lane = t & 31;
    int wm = (w & 1) * 64, wn = (w >> 1) * 32;
    int g = lane >> 2, tg = lane & 3;
    int wphase = w >> 2;  // 0: cols 0-63, 1: cols 64-127
    int bh = blockIdx.y;
    int m0 = blockIdx.x * 128;
    const __nv_bfloat16* xh = g_xhi + (size_t)(bh >> 4) * SS * DD + (bh & 15) * HD;
    const __nv_bfloat16* xl = g_xlo + (size_t)(bh >> 4) * SS * DD + (bh & 15) * HD;

    // stage A once
#pragma unroll
    for (int i = 0; i < 8; i++) {
        int lin = t + i * 256;
        int r = lin >> 4, hh = lin & 15;
        *(uint2*)&aH[r * SA2 + hh * 4] = *(const uint2*)&xh[(size_t)(m0 + r) * DD + hh * 4];
        *(uint2*)&aL[r * SA2 + hh * 4] = *(const uint2*)&xl[(size_t)(m0 + r) * DD + hh * 4];
    }

    float ls[10];
#pragma unroll
    for (int q = 0; q < 10; q++) ls[q] = 1e30f;
    int row_l = t >> 1;        // this thread's row, fixed for whole kernel
    int hhalf = t & 1;         // which 32-col slice within a 64-col phase

    for (int ct = 0; ct < 16; ++ct) {
        stage_cp64(bH, xh + (size_t)ct * 128 * DD, DD, t);
        stage_cp64(bL, xl + (size_t)ct * 128 * DD, DD, t);
        CP_COMMIT();
        CP_WAIT0();
        __syncthreads();
        float acc[4][4][4];
#pragma unroll
        for (int a = 0; a < 4; a++)
#pragma unroll
            for (int b2 = 0; b2 < 4; b2++)
#pragma unroll
                for (int c2 = 0; c2 < 4; c2++) acc[a][b2][c2] = 0.f;
        mma_chunk<SA2, 4, 4>(aH, aL, bH, bL, wm, wn, g, tg, acc);
#pragma unroll
        for (int p = 0; p < 2; p++) {
            if (wphase == p) {
#pragma unroll
                for (int mt = 0; mt < 4; mt++)
#pragma unroll
                    for (int nt = 0; nt < 4; nt++) {
                        float* c = acc[mt][nt];
#pragma unroll
                        for (int half = 0; half < 2; half++) {
                            int ml = wm + mt * 16 + g + half * 8;
                            int nl = wn + nt * 8 + tg * 2;
                            float2 sqj = *(const float2*)&g_sq[bh * SS + ct * 128 + nl];
                            sD[ml * 66 + (nl - p * 64)] = sqj.x - 2.f * c[half * 2];
                            sD[ml * 66 + (nl - p * 64) + 1] = sqj.y - 2.f * c[half * 2 + 1];
                        }
                    }
            }
            __syncthreads();
            const float* rp = &sD[row_l * 66 + hhalf * 32];
#pragma unroll 8
            for (int i = 0; i < 32; ++i) {
                float v = rp[i];
                if (v < ls[9]) {
                    ls[9] = v;
#pragma unroll
                    for (int q = 9; q > 0; --q) {
                        if (ls[q] < ls[q - 1]) { float tm = ls[q]; ls[q] = ls[q - 1]; ls[q - 1] = tm; }
                    }
                }
            }
            __syncthreads();
        }
    }
    // merge the two half-row top-10s
#pragma unroll
    for (int q = 0; q < 10; q++) sD[row_l * 66 + hhalf * 10 + q] = ls[q];
    __syncthreads();
    if (hhalf == 0) {
        const float* a = &sD[row_l * 66];
        const float* b = a + 10;
        int ia = 0, ib = 0;
        float kth = 0.f;
#pragma unroll
        for (int it = 0; it < 10; ++it)
            kth = (a[ia] <= b[ib]) ? a[ia++] : b[ib++];
        int m = m0 + row_l;
        float kd = sqrtf(fmaxf(g_sq[bh * SS + m] + kth, 0.f));
        g_kd[bh * SS + m] = kd;
        atomicMax((int*)&g_kdmax[bh], __float_as_int(kd));
    }
}

// ---------------- K5: tls -----------------------------------------------------
__global__ __launch_bounds__(256) void tls_kernel() {
    int bh = blockIdx.x;
    int t = threadIdx.x;
    float dinv = 1.0f / (g_d2cmax[bh] + 1e-8f);
    float kinv = 1.0f / (g_kdmax[bh] + 1e-8f);
    for (int s = t; s < SS; s += 256) {
        float life = g_d2c[bh * SS + s] * dinv;
        float mmd = g_kd[bh * SS + s] * kinv;
        g_tls[bh * SS + s] = 0.7f * life + 0.3f * mmd;
    }
}

// ---------------- K6: bitonic sort + mark -------------------------------------
__global__ __launch_bounds__(1024) void sort_mark_kernel() {
    __shared__ float a[SS];
    int t = threadIdx.x;
    int bh = blockIdx.x;
    a[t] = g_tls[bh * SS + t];
    a[t + 1024] = g_tls[bh * SS + t + 1024];
    __syncthreads();
    for (int k = 2; k <= SS; k <<= 1) {
        for (int j = k >> 1; j > 0; j >>= 1) {
#pragma unroll
            for (int half = 0; half < 2; ++half) {
                int i = t + half * 1024;
                int ixj = i ^ j;
                if (ixj > i) {
                    bool up = ((i & k) == 0);
                    float xi = a[i], xj = a[ixj];
                    if (up ? (xi > xj) : (xi < xj)) { a[i] = xj; a[ixj] = xi; }
                }
            }
            __syncthreads();
        }
    }
    float thresh = a[SS - NKEEP];
    __syncthreads();
#pragma unroll
    for (int half = 0; half < 2; ++half) {
        int s = t + half * 1024;
        g_mark[bh * SS + s] = (g_tls[bh * SS + s] >= thresh) ? 1 : 0;
    }
}

// ---------------- K7: score GEMM (single 64-wide chunk, occ 2) ----------------
#define SCORE_SMEM (4 * T64)
__global__ __launch_bounds__(256, 2) void score_mma(float* __restrict__ attn) {
    extern __shared__ char dsm[];
    __nv_bfloat16* qH = (__nv_bfloat16*)dsm;
    __nv_bfloat16* qL = (__nv_bfloat16*)(dsm + T64);
    __nv_bfloat16* kH = (__nv_bfloat16*)(dsm + 2 * T64);
    __nv_bfloat16* kL = (__nv_bfloat16*)(dsm + 3 * T64);
    int t = threadIdx.x, w = t >> 5, lane = t & 31;
    int wm = (w & 1) * 64, wn = (w >> 1) * 32;
    int g = lane >> 2, tg = lane & 3;
    float acc[4][4][4] = {};
    int bx = blockIdx.x, by = blockIdx.y, bh = blockIdx.z;
    size_t qo = ((size_t)bh * SS + by * 128) * HD;
    size_t ko = ((size_t)bh * SS + bx * 128) * HD;
    stage_cp64(qH, g_qhi + qo, HD, t);
    stage_cp64(qL, g_qlo + qo, HD, t);
    stage_cp64(kH, g_khi + ko, HD, t);
    stage_cp64(kL, g_klo + ko, HD, t);
    CP_COMMIT();
    CP_WAIT0();
    __syncthreads();
    mma_chunk<SA2, 4, 3>(qH, qL, kH, kL, wm, wn, g, tg, acc);
    float* abase = attn + (size_t)bh * SS * SS;
#pragma unroll
    for (int mt = 0; mt < 4; mt++)
#pragma unroll
        for (int nt = 0; nt < 4; nt++) {
            float* c = acc[mt][nt];
#pragma unroll
            for (int half = 0; half < 2; half++) {
                int m = by * 128 + wm + mt * 16 + g + half * 8;
                int n = bx * 128 + wn + nt * 8 + tg * 2;
                float2 o;
                o.x = c[half * 2];
                o.y = c[half * 2 + 1];
                *(float2*)&abase[(size_t)m * SS + n] = o;
            }
        }
}

// ---------------- K8: masked softmax (exp cached in smem) ---------------------
__global__ __launch_bounds__(256) void softmax_kernel(float* __restrict__ attn) {
    extern __shared__ float smemf[];
    float* rows = smemf;
    unsigned char* mk = (unsigned char*)(rows + 8 * SS);
    int bh = blockIdx.y;
    int t = threadIdx.x, w = t >> 5, lane = t & 31;
    int i = blockIdx.x * 8 + w;
    for (int j = t; j < SS; j += 256) mk[j] = (unsigned char)g_mark[bh * SS + j];
    float* gp = attn + ((size_t)bh * SS + i) * SS;
    float* rb = rows + w * SS;
    for (int it = 0; it < 64; ++it) rb[lane + it * 32] = gp[lane + it * 32];
    __syncthreads();
    float m = -1e30f;
    for (int it = 0; it < 64; ++it) {
        int j = lane + it * 32;
        int rel = j - i;
        bool ms = (rel >= -W2 && rel <= W2) || mk[j];
        if (ms) m = fmaxf(m, rb[j]);
    }
#pragma unroll
    for (int off = 16; off; off >>= 1) m = fmaxf(m, __shfl_xor_sync(0xffffffffu, m, off));
    float sum = 0.f;
    for (int it = 0; it < 64; ++it) {
        int j = lane + it * 32;
        int rel = j - i;
        bool ms = (rel >= -W2 && rel <= W2) || mk[j];
        if (ms) {
            float e = __expf(rb[j] - m);
            rb[j] = e;       // cache exp for the write pass
            sum += e;
        }
    }
#pragma unroll
    for (int off = 16; off; off >>= 1) sum += __shfl_xor_sync(0xffffffffu, sum, off);
    float inv = 1.0f / sum;
    for (int it = 0; it < 64; ++it) {
        int j = lane + it * 32;
        int rel = j - i;
        bool ms = (rel >= -W2 && rel <= W2) || mk[j];
        gp[j] = ms ? rb[j] * inv : 0.f;
    }
}

// ---------------- K9: AV GEMM (pipelined, fused passes) -----------------------
__global__ __launch_bounds__(256, 2) void av_mma(const float* __restrict__ attn) {
    __shared__ __nv_bfloat16 sAh[128 * SA], sAl[128 * SA];
    __shared__ __nv_bfloat16 sVh[2][64 * SA], sVl[2][64 * SA];
    int t = threadIdx.x, w = t >> 5, lane = t & 31;
    int wm = (w & 1) * 64, wn = (w >> 1) * 16;
    int g = lane >> 2, tg = lane & 3;
    int bx = blockIdx.x, bh = blockIdx.y;
    const float* Ap = attn + ((size_t)bh * SS + bx * 128) * SS;
    const __nv_bfloat16* Vh = g_vthi + (size_t)bh * HD * SS;
    const __nv_bfloat16* Vl = g_vtlo + (size_t)bh * HD * SS;

    float2 pv[8];
#pragma unroll
    for (int i = 0; i < 8; i++) {
        int lin = t + i * 256;
        int r = lin >> 4, h = lin & 15;
        pv[i] = *(const float2*)&Ap[(size_t)r * SS + h * 2];
    }
#pragma unroll
    for (int i = 0; i < 2; i++) {
        int lin = t + i * 256;
        int r = lin >> 3, h = lin & 7;
        cp8(&sVh[0][r * SA + h * 4], &Vh[(size_t)r * SS + h * 4]);
        cp8(&sVl[0][r * SA + h * 4], &Vl[(size_t)r * SS + h * 4]);
    }
    CP_COMMIT();

    float acc[4][2][4] = {};
    for (int ch = 0; ch < SS / 32; ++ch) {
        int buf = ch & 1;
        __syncthreads();
#pragma unroll
        for (int i = 0; i < 8; i++) {
            int lin = t + i * 256;
            int r = lin >> 4, h = lin & 15;
            uint32_t hi, lo;
            split2(pv[i].x, pv[i].y, hi, lo);
            *(uint32_t*)&sAh[r * SA + h * 2] = hi;
            *(uint32_t*)&sAl[r * SA + h * 2] = lo;
        }
        if (ch + 1 < SS / 32) {
            int k0n = (ch + 1) * 32;
#pragma unroll
            for (int i = 0; i < 2; i++) {
                int lin = t + i * 256;
                int r = lin >> 3, h = lin & 7;
                cp8(&sVh[buf ^ 1][r * SA + h * 4], &Vh[(size_t)r * SS + k0n + h * 4]);
                cp8(&sVl[buf ^ 1][r * SA + h * 4], &Vl[(size_t)r * SS + k0n + h * 4]);
            }
            CP_COMMIT();
#pragma unroll
            for (int i = 0; i < 8; i++) {
                int lin = t + i * 256;
                int r = lin >> 4, h = lin & 15;
                pv[i] = *(const float2*)&Ap[(size_t)r * SS + k0n + h * 2];
            }
            CP_WAIT1();
        } else {
            CP_WAIT0();
        }
        __syncthreads();
        const __nv_bfloat16* Bh2 = sVh[buf];
        const __nv_bfloat16* Bl2 = sVl[buf];
#pragma unroll
        for (int s = 0; s < 2; s++) {
            int kk = s * 16;
            uint32_t ah[4][4], al[4][4], bhf[2][2], blf[2][2];
#pragma unroll
            for (int mt = 0; mt < 4; mt++) {
                int r0 = (wm + mt * 16 + g) * SA + kk + tg * 2;
                ah[mt][0] = *(const uint32_t*)&sAh[r0];
                ah[mt][1] = *(const uint32_t*)&sAh[r0 + 8 * SA];
                ah[mt][2] = *(const uint32_t*)&sAh[r0 + 8];
                ah[mt][3] = *(const uint32_t*)&sAh[r0 + 8 * SA + 8];
                al[mt][0] = *(const uint32_t*)&sAl[r0];
                al[mt][1] = *(const uint32_t*)&sAl[r0 + 8 * SA];
                al[mt][2] = *(const uint32_t*)&sAl[r0 + 8];
                al[mt][3] = *(const uint32_t*)&sAl[r0 + 8 * SA + 8];
            }
#pragma unroll
            for (int nt = 0; nt < 2; nt++) {
                int rb = (wn + nt * 8 + g) * SA + kk + tg * 2;
                bhf[nt][0] = *(const uint32_t*)&Bh2[rb];
                bhf[nt][1] = *(const uint32_t*)&Bh2[rb + 8];
                blf[nt][0] = *(const uint32_t*)&Bl2[rb];
                blf[nt][1] = *(const uint32_t*)&Bl2[rb + 8];
            }
#pragma unroll
            for (int nt = 0; nt < 2; nt++)
#pragma unroll
                for (int mt = 0; mt < 4; mt++) {
                    mma16816(acc[mt][nt], ah[mt], bhf[nt]);
                    mma16816(acc[mt][nt], ah[mt], blf[nt]);
                    mma16816(acc[mt][nt], al[mt], bhf[nt]);
                }
        }
    }
    int b = bh >> 4, h = bh & 15;
#pragma unroll
    for (int mt = 0; mt < 4; mt++)
#pragma unroll
        for (int nt = 0; nt < 2; nt++) {
            float* c = acc[mt][nt];
#pragma unroll
            for (int half = 0; half < 2; half++) {
                int s = bx * 128 + wm + mt * 16 + g + half * 8;
                int d = wn + nt * 8 + tg * 2;
                size_t di = ((size_t)(b * SS + s)) * DD + h * 64 + d;
                uint32_t hi, lo;
                split2(c[half * 2], c[half * 2 + 1], hi, lo);
                *(uint32_t*)&g_ohi[di] = hi;
                *(uint32_t*)&g_olo[di] = lo;
            }
        }
}

// ---------------- K10: output projection --------------------------------------
__global__ __launch_bounds__(256, 2) void proj_mma(const float* __restrict__ bias,
                                                   float* __restrict__ out) {
    GEMM_PROLOG();
    int bx = blockIdx.x, by = blockIdx.y;
    gemm_db(g_ohi + (size_t)by * 128 * DD, g_olo + (size_t)by * 128 * DD, DD,
            g_w1hi + (size_t)bx * 128 * DD, g_w1lo + (size_t)bx * 128 * DD, DD,
            DD, dsm, t, wm, wn, g, tg, acc);
#pragma unroll
    for (int mt = 0; mt < 4; mt++)
#pragma unroll
        for (int nt = 0; nt < 4; nt++) {
            float* c = acc[mt][nt];
#pragma unroll
            for (int half = 0; half < 2; half++) {
                int m = by * 128 + wm + mt * 16 + g + half * 8;
                int n = bx * 128 + wn + nt * 8 + tg * 2;
                float2 o;
                o.x = c[half * 2] + bias[n];
                o.y = c[half * 2 + 1] + bias[n + 1];
                *(float2*)&out[(size_t)m * DD + n] = o;
            }
        }
}

// ---------------- launch ------------------------------------------------------
extern "C" void kernel_launch(void* const* d_in, const int* in_sizes, int n_in,
                              void* d_out, int out_size) {
    const float* x = (const float*)d_in[0];
    const float* qkv_w = (const float*)d_in[1];
    const float* qkv_b = (const float*)d_in[2];
    const float* out_w = (const float*)d_in[3];
    const float* out_b = (const float*)d_in[4];
    float* out = (float*)d_out;
    float* attn = out + (size_t)BB * SS * DD;

    const int SM_SMEM = 8 * SS * 4 + SS;
    cudaFuncSetAttribute(softmax_kernel, cudaFuncAttributeMaxDynamicSharedMemorySize, SM_SMEM);
    cudaFuncSetAttribute(qkv_mma, cudaFuncAttributeMaxDynamicSharedMemorySize, GEMM_DSMEM);
    cudaFuncSetAttribute(score_mma, cudaFuncAttributeMaxDynamicSharedMemorySize, SCORE_SMEM);
    cudaFuncSetAttribute(proj_mma, cudaFuncAttributeMaxDynamicSharedMemorySize, GEMM_DSMEM);
    cudaFuncSetAttribute(distkth_mma, cudaFuncAttributeMaxDynamicSharedMemorySize, DIST_SMEM);

    cvt_x<<<(BB * SS * DD + 255) / 256, 256>>>(x);
    cvt_w3<<<(3 * DD * DD + 255) / 256, 256>>>(qkv_w);
    cvt_w1<<<(DD * DD + 255) / 256, 256>>>(out_w);

    qkv_mma<<<dim3(24, 32), 256, GEMM_DSMEM>>>(qkv_b);
    stats_kernel<<<BH, 256>>>(x);
    distkth_mma<<<dim3(16, BH), 256, DIST_SMEM>>>();
    tls_kernel<<<BH, 256>>>();
    sort_mark_kernel<<<BH, 1024>>>();
    score_mma<<<dim3(16, 16, BH), 256, SCORE_SMEM>>>(attn);
    softmax_kernel<<<dim3(SS / 8, BH), 256, SM_SMEM>>>(attn);
    av_mma<<<dim3(16, BH), 256>>>(attn);
    proj_mma<<<dim3(8, 32), 256, GEMM_DSMEM>>>(out_b, out);
}

// round 9
// speedup vs baseline: 5.5035x; 1.0322x over previous
#include <cuda_runtime.h>
#include <cuda_bf16.h>
#include <math.h>
#include <stdint.h>

#define BB 2
#define SS 2048
#define DD 1024
#define HH 16
#define HD 64
#define BH (BB*HH)
#define NKEEP 675
#define W2 64
#define SA 40   // smem row stride (bf16), 32-wide K chunks
#define SA2 72  // smem row stride (bf16), 64-wide K chunks

// ---------------- scratch -----------------------------------------------------
__device__ float g_sq[BH*SS];
__device__ float g_d2c[BH*SS];
__device__ float g_d2cmax[BH];
__device__ float g_kd[BH*SS];
__device__ float g_kdmax[BH];
__device__ float g_tls[BH*SS];
__device__ int   g_mark[BH*SS];

__device__ __align__(256) __nv_bfloat16 g_xhi[BB*SS*DD];
__device__ __align__(256) __nv_bfloat16 g_xlo[BB*SS*DD];
__device__ __align__(256) __nv_bfloat16 g_w3hi[3*DD*DD];
__device__ __align__(256) __nv_bfloat16 g_w3lo[3*DD*DD];
__device__ __align__(256) __nv_bfloat16 g_w1hi[DD*DD];
__device__ __align__(256) __nv_bfloat16 g_w1lo[DD*DD];
__device__ __align__(256) __nv_bfloat16 g_qhi[BH*SS*HD];
__device__ __align__(256) __nv_bfloat16 g_qlo[BH*SS*HD];
__device__ __align__(256) __nv_bfloat16 g_khi[BH*SS*HD];
__device__ __align__(256) __nv_bfloat16 g_klo[BH*SS*HD];
__device__ __align__(256) __nv_bfloat16 g_vthi[BH*HD*SS];  // V^T: [bh][d][s]
__device__ __align__(256) __nv_bfloat16 g_vtlo[BH*HD*SS];
__device__ __align__(256) __nv_bfloat16 g_ohi[BB*SS*DD];
__device__ __align__(256) __nv_bfloat16 g_olo[BB*SS*DD];

// ---------------- helpers -----------------------------------------------------
__device__ __forceinline__ uint32_t s2u(const void* p) {
    uint32_t a;
    asm("{ .reg .u64 t; cvta.to.shared.u64 t, %1; cvt.u32.u64 %0, t; }" : "=r"(a) : "l"(p));
    return a;
}
__device__ __forceinline__ void mma16816(float* c, const uint32_t* a, const uint32_t* b) {
    asm volatile(
        "mma.sync.aligned.m16n8k16.row.col.f32.bf16.bf16.f32 "
        "{%0,%1,%2,%3}, {%4,%5,%6,%7}, {%8,%9}, {%0,%1,%2,%3};"
        : "+f"(c[0]), "+f"(c[1]), "+f"(c[2]), "+f"(c[3])
        : "r"(a[0]), "r"(a[1]), "r"(a[2]), "r"(a[3]), "r"(b[0]), "r"(b[1]));
}
__device__ __forceinline__ void ldsm_x4(uint32_t* r, uint32_t addr) {
    asm volatile("ldmatrix.sync.aligned.m8n8.x4.shared.b16 {%0,%1,%2,%3}, [%4];"
                 : "=r"(r[0]), "=r"(r[1]), "=r"(r[2]), "=r"(r[3]) : "r"(addr));
}
__device__ __forceinline__ void split2(float x, float y, uint32_t& hi, uint32_t& lo) {
    __nv_bfloat16 hx = __float2bfloat16(x), hy = __float2bfloat16(y);
    __nv_bfloat162 h, l;
    h.x = hx; h.y = hy;
    l.x = __float2bfloat16(x - __bfloat162float(hx));
    l.y = __float2bfloat16(y - __bfloat162float(hy));
    hi = *(uint32_t*)&h;
    lo = *(uint32_t*)&l;
}
__device__ __forceinline__ void cp8(__nv_bfloat16* dst, const __nv_bfloat16* src) {
    uint32_t d = s2u(dst);
    asm volatile("cp.async.ca.shared.global [%0], [%1], 8;" :: "r"(d), "l"(src) : "memory");
}
#define CP_COMMIT() asm volatile("cp.async.commit_group;" ::: "memory")
#define CP_WAIT1() asm volatile("cp.async.wait_group 1;" ::: "memory")
#define CP_WAIT0() asm volatile("cp.async.wait_group 0;" ::: "memory")

// cp.async stage of a [128 x 32] bf16 tile -> smem [128][SA]
__device__ __forceinline__ void stage_cp(__nv_bfloat16* dst, const __nv_bfloat16* src,
                                         int ld, int k0, int t) {
#pragma unroll
    for (int i = 0; i < 4; i++) {
        int lin = t + i * 256;
        int r = lin >> 3, h = lin & 7;
        cp8(&dst[r * SA + h * 4], &src[(size_t)r * ld + k0 + h * 4]);
    }
}
// cp.async stage of a [128 x 64] bf16 tile -> smem [128][SA2]
__device__ __forceinline__ void stage_cp64(__nv_bfloat16* dst, const __nv_bfloat16* src,
                                           int ld, int t) {
#pragma unroll
    for (int i = 0; i < 8; i++) {
        int lin = t + i * 256;
        int r = lin >> 4, h = lin & 15;
        cp8(&dst[r * SA2 + h * 4], &src[(size_t)r * ld + h * 4]);
    }
}

// ---- fused-pass MMA over one K chunk via ldmatrix ----------------------------
// A x4: quads -> {r0-7,k0-7},{r8-15,k0-7},{r0-7,k8-15},{r8-15,k8-15}
// B x4: quads -> {n0-7,k0-7},{n0-7,k8-15},{n8-15,k0-7},{n8-15,k8-15}
template<int STR, int NSTEP, int NPASS>
__device__ __forceinline__ void mma_chunk(uint32_t Ah, uint32_t Al,
                                          uint32_t Bh, uint32_t Bl,
                                          int wm, int wn, int lane, float (*acc)[4][4]) {
    int quad = lane >> 3, within = lane & 7;
    int arow = (wm + within + (quad & 1) * 8) * STR + (quad >> 1) * 8;
    int brow = (wn + within + (quad >> 1) * 8) * STR + (quad & 1) * 8;
#pragma unroll
    for (int s = 0; s < NSTEP; s++) {
        int kk = s * 16;
        uint32_t ah[4][4], al[4][4], bh[2][4], bl[2][4];
#pragma unroll
        for (int mt = 0; mt < 4; mt++) {
            uint32_t off = (uint32_t)(arow + mt * 16 * STR + kk) * 2;
            ldsm_x4(ah[mt], Ah + off);
            ldsm_x4(al[mt], Al + off);
        }
#pragma unroll
        for (int np = 0; np < 2; np++) {
            uint32_t off = (uint32_t)(brow + np * 16 * STR + kk) * 2;
            ldsm_x4(bh[np], Bh + off);
            ldsm_x4(bl[np], Bl + off);
        }
#pragma unroll
        for (int nt = 0; nt < 4; nt++) {
            const uint32_t* bhp = &bh[nt >> 1][(nt & 1) * 2];
            const uint32_t* blp = &bl[nt >> 1][(nt & 1) * 2];
#pragma unroll
            for (int mt = 0; mt < 4; mt++) {
                mma16816(acc[mt][nt], ah[mt], bhp);
                mma16816(acc[mt][nt], ah[mt], blp);
                mma16816(acc[mt][nt], al[mt], bhp);
                if (NPASS == 4) mma16816(acc[mt][nt], al[mt], blp);
            }
        }
    }
}

// double-buffered mainloop for K>=128 GEMMs (tiles: 0=Ahi 1=Alo 2=Bhi 3=Blo)
#define TILE_BYTES (128 * SA * 2)
__device__ __forceinline__ void gemm_db(const __nv_bfloat16* Ahi, const __nv_bfloat16* Alo, int lda,
                                        const __nv_bfloat16* Bhi, const __nv_bfloat16* Blo, int ldb,
                                        int K, char* dsm, int t, int wm, int wn,
                                        int lane, float (*acc)[4][4]) {
    uint32_t base = s2u(dsm);
    auto tile = [&](int buf, int idx) {
        return (__nv_bfloat16*)(dsm + (buf * 4 + idx) * TILE_BYTES);
    };
    stage_cp(tile(0, 0), Ahi, lda, 0, t);
    stage_cp(tile(0, 1), Alo, lda, 0, t);
    stage_cp(tile(0, 2), Bhi, ldb, 0, t);
    stage_cp(tile(0, 3), Blo, ldb, 0, t);
    CP_COMMIT();
    int nch = K / 32;
    for (int ch = 0; ch < nch; ++ch) {
        int buf = ch & 1;
        if (ch + 1 < nch) {
            int nb = buf ^ 1, k0 = (ch + 1) * 32;
            stage_cp(tile(nb, 0), Ahi, lda, k0, t);
            stage_cp(tile(nb, 1), Alo, lda, k0, t);
            stage_cp(tile(nb, 2), Bhi, ldb, k0, t);
            stage_cp(tile(nb, 3), Blo, ldb, k0, t);
            CP_COMMIT();
            CP_WAIT1();
        } else {
            CP_WAIT0();
        }
        __syncthreads();
        uint32_t tb = base + buf * 4 * TILE_BYTES;
        mma_chunk<SA, 2, 3>(tb, tb + TILE_BYTES, tb + 2 * TILE_BYTES, tb + 3 * TILE_BYTES,
                            wm, wn, lane, acc);
        __syncthreads();
    }
}
#define GEMM_DSMEM (8 * TILE_BYTES)

#define GEMM_PROLOG() \
    extern __shared__ char dsm[]; \
    int t = threadIdx.x, w = t >> 5, lane = t & 31; \
    int wm = (w & 1) * 64, wn = (w >> 1) * 32; \
    int g = lane >> 2, tg = lane & 3; \
    float acc[4][4][4] = {};

// ---------------- cvt: fp32 -> (hi, lo) bf16 ----------------------------------
__global__ __launch_bounds__(256) void cvt_x(const float* __restrict__ s) {
    int i = blockIdx.x * 256 + threadIdx.x;
    if (i < BB * SS * DD) {
        float v = s[i];
        __nv_bfloat16 h = __float2bfloat16(v);
        g_xhi[i] = h;
        g_xlo[i] = __float2bfloat16(v - __bfloat162float(h));
    }
}
__global__ __launch_bounds__(256) void cvt_w3(const float* __restrict__ s) {
    int i = blockIdx.x * 256 + threadIdx.x;
    if (i < 3 * DD * DD) {
        float v = s[i];
        __nv_bfloat16 h = __float2bfloat16(v);
        g_w3hi[i] = h;
        g_w3lo[i] = __float2bfloat16(v - __bfloat162float(h));
    }
}
__global__ __launch_bounds__(256) void cvt_w1(const float* __restrict__ s) {
    int i = blockIdx.x * 256 + threadIdx.x;
    if (i < DD * DD) {
        float v = s[i];
        __nv_bfloat16 h = __float2bfloat16(v);
        g_w1hi[i] = h;
        g_w1lo[i] = __float2bfloat16(v - __bfloat162float(h));
    }
}

// ---------------- K1: QKV GEMM ------------------------------------------------
__global__ __launch_bounds__(256, 2) void qkv_mma(const float* __restrict__ bias) {
    GEMM_PROLOG();
    int bx = blockIdx.x, by = blockIdx.y;
    gemm_db(g_xhi + (size_t)by * 128 * DD, g_xlo + (size_t)by * 128 * DD, DD,
            g_w3hi + (size_t)bx * 128 * DD, g_w3lo + (size_t)bx * 128 * DD, DD,
            DD, dsm, t, wm, wn, lane, acc);
#pragma unroll
    for (int mt = 0; mt < 4; mt++)
#pragma unroll
        for (int nt = 0; nt < 4; nt++) {
            float* c = acc[mt][nt];
#pragma unroll
            for (int half = 0; half < 2; half++) {
                int m = by * 128 + wm + mt * 16 + g + half * 8;
                int n = bx * 128 + wn + nt * 8 + tg * 2;
                float v0 = c[half * 2] + bias[n];
                float v1 = c[half * 2 + 1] + bias[n + 1];
                int which = n >> 10, h = (n >> 6) & 15, d = n & 63;
                int b = m >> 11, s = m & (SS - 1);
                int bh = b * HH + h;
                if (which == 0) {
                    size_t di = ((size_t)bh * SS + s) * HD + d;
                    uint32_t hi, lo;
                    split2(v0 * 0.125f, v1 * 0.125f, hi, lo);
                    *(uint32_t*)&g_qhi[di] = hi;
                    *(uint32_t*)&g_qlo[di] = lo;
                } else if (which == 1) {
                    size_t di = ((size_t)bh * SS + s) * HD + d;
                    uint32_t hi, lo;
                    split2(v0, v1, hi, lo);
                    *(uint32_t*)&g_khi[di] = hi;
                    *(uint32_t*)&g_klo[di] = lo;
                } else {
                    size_t di = ((size_t)bh * HD + d) * SS + s;
                    __nv_bfloat16 h0 = __float2bfloat16(v0), h1 = __float2bfloat16(v1);
                    g_vthi[di] = h0;
                    g_vtlo[di] = __float2bfloat16(v0 - __bfloat162float(h0));
                    g_vthi[di + SS] = h1;
                    g_vtlo[di + SS] = __float2bfloat16(v1 - __bfloat162float(h1));
                }
            }
        }
}

// ---------------- K2: stats ---------------------------------------------------
__global__ __launch_bounds__(256) void stats_kernel(const float* __restrict__ x) {
    int bh = blockIdx.x;
    int b = bh / HH, h = bh % HH;
    int t = threadIdx.x;
    __shared__ float part[256];
    __shared__ float cent[64];
    int d = t & 63, grp = t >> 6;
    float acc = 0.f;
    for (int s = grp; s < SS; s += 4)
        acc += x[((size_t)(b * SS + s)) * DD + h * HD + d];
    part[t] = acc;
    __syncthreads();
    if (t < 64) cent[t] = (part[t] + part[t + 64] + part[t + 128] + part[t + 192]) * (1.0f / SS);
    __syncthreads();
    float lmax = 0.f;
    for (int s = t; s < SS; s += 256) {
        const float* xp = x + (size_t)(b * SS + s) * DD + h * HD;
        float sq = 0.f, dc2 = 0.f;
#pragma unroll
        for (int dd = 0; dd < HD; ++dd) {
            float v = xp[dd];
            sq += v * v;
            float wv = v - cent[dd];
            dc2 += wv * wv;
        }
        g_sq[bh * SS + s] = sq;
        float dc = sqrtf(dc2);
        g_d2c[bh * SS + s] = dc;
        lmax = fmaxf(lmax, dc);
    }
    __syncthreads();
    part[t] = lmax;
    __syncthreads();
    for (int off = 128; off > 0; off >>= 1) {
        if (t < off) part[t] = fmaxf(part[t], part[t + off]);
        __syncthreads();
    }
    if (t == 0) {
        g_d2cmax[bh] = part[0];
        g_kdmax[bh] = 0.f;
    }
}

// ---------------- K3+K4 fused: pairwise dist + 10th-smallest (occ 2) ----------
#define T64 (128 * SA2 * 2)
#define DK_SD (4 * T64)
#define DIST_SMEM (DK_SD + 128 * 66 * 4)
__global__ __launch_bounds__(256, 2) void distkth_mma() {
    extern __shared__ char dsm[];
    uint32_t base = s2u(dsm);
    __nv_bfloat16* aH = (__nv_bfloat16*)dsm;
    __nv_bfloat16* aL = (__nv_bfloat16*)(dsm + T64);
    __nv_bfloat16* bH = (__nv_bfloat16*)(dsm + 2 * T64);
    __nv_bfloat16* bL = (__nv_bfloat16*)(dsm + 3 * T64);
    float* sD = (float*)(dsm + DK_SD);
    int t = threadIdx.x, w = t >> 5, lane = t & 31;
    int wm = (w & 1) * 64, wn = (w >> 1) * 32;
    int g = lane >> 2, tg = lane & 3;
    int wphase = w >> 2;
    int bh = blockIdx.y;
    int m0 = blockIdx.x * 128;
    const __nv_bfloat16* xh = g_xhi + (size_t)(bh >> 4) * SS * DD + (bh & 15) * HD;
    const __nv_bfloat16* xl = g_xlo + (size_t)(bh >> 4) * SS * DD + (bh & 15) * HD;

#pragma unroll
    for (int i = 0; i < 8; i++) {
        int lin = t + i * 256;
        int r = lin >> 4, hh = lin & 15;
        *(uint2*)&aH[r * SA2 + hh * 4] = *(const uint2*)&xh[(size_t)(m0 + r) * DD + hh * 4];
        *(uint2*)&aL[r * SA2 + hh * 4] = *(const uint2*)&xl[(size_t)(m0 + r) * DD + hh * 4];
    }

    float ls[10];
#pragma unroll
    for (int q = 0; q < 10; q++) ls[q] = 1e30f;
    int row_l = t >> 1;
    int hhalf = t & 1;

    for (int ct = 0; ct < 16; ++ct) {
        stage_cp64(bH, xh + (size_t)ct * 128 * DD, DD, t);
        stage_cp64(bL, xl + (size_t)ct * 128 * DD, DD, t);
        CP_COMMIT();
        CP_WAIT0();
        __syncthreads();
        float acc[4][4][4];
#pragma unroll
        for (int a = 0; a < 4; a++)
#pragma unroll
            for (int b2 = 0; b2 < 4; b2++)
#pragma unroll
                for (int c2 = 0; c2 < 4; c2++) acc[a][b2][c2] = 0.f;
        mma_chunk<SA2, 4, 4>(base, base + T64, base + 2 * T64, base + 3 * T64,
                             wm, wn, lane, acc);
#pragma unroll
        for (int p = 0; p < 2; p++) {
            if (wphase == p) {
#pragma unroll
                for (int mt = 0; mt < 4; mt++)
#pragma unroll
                    for (int nt = 0; nt < 4; nt++) {
                        float* c = acc[mt][nt];
#pragma unroll
                        for (int half = 0; half < 2; half++) {
                            int ml = wm + mt * 16 + g + half * 8;
                            int nl = wn + nt * 8 + tg * 2;
                            float2 sqj = *(const float2*)&g_sq[bh * SS + ct * 128 + nl];
                            sD[ml * 66 + (nl - p * 64)] = sqj.x - 2.f * c[half * 2];
                            sD[ml * 66 + (nl - p * 64) + 1] = sqj.y - 2.f * c[half * 2 + 1];
                        }
                    }
            }
            __syncthreads();
            const float* rp = &sD[row_l * 66 + hhalf * 32];
#pragma unroll 8
            for (int i = 0; i < 32; ++i) {
                float v = rp[i];
                if (v < ls[9]) {
                    ls[9] = v;
#pragma unroll
                    for (int q = 9; q > 0; --q) {
                        if (ls[q] < ls[q - 1]) { float tm = ls[q]; ls[q] = ls[q - 1]; ls[q - 1] = tm; }
                    }
                }
            }
            __syncthreads();
        }
    }
#pragma unroll
    for (int q = 0; q < 10; q++) sD[row_l * 66 + hhalf * 10 + q] = ls[q];
    __syncthreads();
    if (hhalf == 0) {
        const float* a = &sD[row_l * 66];
        const float* b = a + 10;
        int ia = 0, ib = 0;
        float kth = 0.f;
#pragma unroll
        for (int it = 0; it < 10; ++it)
            kth = (a[ia] <= b[ib]) ? a[ia++] : b[ib++];
        int m = m0 + row_l;
        float kd = sqrtf(fmaxf(g_sq[bh * SS + m] + kth, 0.f));
        g_kd[bh * SS + m] = kd;
        atomicMax((int*)&g_kdmax[bh], __float_as_int(kd));
    }
}

// ---------------- K5: tls -----------------------------------------------------
__global__ __launch_bounds__(256) void tls_kernel() {
    int bh = blockIdx.x;
    int t = threadIdx.x;
    float dinv = 1.0f / (g_d2cmax[bh] + 1e-8f);
    float kinv = 1.0f / (g_kdmax[bh] + 1e-8f);
    for (int s = t; s < SS; s += 256) {
        float life = g_d2c[bh * SS + s] * dinv;
        float mmd = g_kd[bh * SS + s] * kinv;
        g_tls[bh * SS + s] = 0.7f * life + 0.3f * mmd;
    }
}

// ---------------- K6: bitonic sort + mark -------------------------------------
__global__ __launch_bounds__(1024) void sort_mark_kernel() {
    __shared__ float a[SS];
    int t = threadIdx.x;
    int bh = blockIdx.x;
    a[t] = g_tls[bh * SS + t];
    a[t + 1024] = g_tls[bh * SS + t + 1024];
    __syncthreads();
    for (int k = 2; k <= SS; k <<= 1) {
        for (int j = k >> 1; j > 0; j >>= 1) {
#pragma unroll
            for (int half = 0; half < 2; ++half) {
                int i = t + half * 1024;
                int ixj = i ^ j;
                if (ixj > i) {
                    bool up = ((i & k) == 0);
                    float xi = a[i], xj = a[ixj];
                    if (up ? (xi > xj) : (xi < xj)) { a[i] = xj; a[ixj] = xi; }
                }
            }
            __syncthreads();
        }
    }
    float thresh = a[SS - NKEEP];
    __syncthreads();
#pragma unroll
    for (int half = 0; half < 2; ++half) {
        int s = t + half * 1024;
        g_mark[bh * SS + s] = (g_tls[bh * SS + s] >= thresh) ? 1 : 0;
    }
}

// ---------------- K7: score GEMM (single 64-wide chunk, occ 2) ----------------
#define SCORE_SMEM (4 * T64)
__global__ __launch_bounds__(256, 2) void score_mma(float* __restrict__ attn) {
    extern __shared__ char dsm[];
    uint32_t base = s2u(dsm);
    __nv_bfloat16* qH = (__nv_bfloat16*)dsm;
    __nv_bfloat16* qL = (__nv_bfloat16*)(dsm + T64);
    __nv_bfloat16* kH = (__nv_bfloat16*)(dsm + 2 * T64);
    __nv_bfloat16* kL = (__nv_bfloat16*)(dsm + 3 * T64);
    int t = threadIdx.x, w = t >> 5, lane = t & 31;
    int wm = (w & 1) * 64, wn = (w >> 1) * 32;
    int g = lane >> 2, tg = lane & 3;
    float acc[4][4][4] = {};
    int bx = blockIdx.x, by = blockIdx.y, bh = blockIdx.z;
    size_t qo = ((size_t)bh * SS + by * 128) * HD;
    size_t ko = ((size_t)bh * SS + bx * 128) * HD;
    stage_cp64(qH, g_qhi + qo, HD, t);
    stage_cp64(qL, g_qlo + qo, HD, t);
    stage_cp64(kH, g_khi + ko, HD, t);
    stage_cp64(kL, g_klo + ko, HD, t);
    CP_COMMIT();
    CP_WAIT0();
    __syncthreads();
    mma_chunk<SA2, 4, 3>(base, base + T64, base + 2 * T64, base + 3 * T64,
                         wm, wn, lane, acc);
    float* abase = attn + (size_t)bh * SS * SS;
#pragma unroll
    for (int mt = 0; mt < 4; mt++)
#pragma unroll
        for (int nt = 0; nt < 4; nt++) {
            float* c = acc[mt][nt];
#pragma unroll
            for (int half = 0; half < 2; half++) {
                int m = by * 128 + wm + mt * 16 + g + half * 8;
                int n = bx * 128 + wn + nt * 8 + tg * 2;
                float2 o;
                o.x = c[half * 2];
                o.y = c[half * 2 + 1];
                *(float2*)&abase[(size_t)m * SS + n] = o;
            }
        }
}

// ---------------- K8: masked softmax (exp cached in smem) ---------------------
__global__ __launch_bounds__(256) void softmax_kernel(float* __restrict__ attn) {
    extern __shared__ float smemf[];
    float* rows = smemf;
    unsigned char* mk = (unsigned char*)(rows + 8 * SS);
    int bh = blockIdx.y;
    int t = threadIdx.x, w = t >> 5, lane = t & 31;
    int i = blockIdx.x * 8 + w;
    for (int j = t; j < SS; j += 256) mk[j] = (unsigned char)g_mark[bh * SS + j];
    float* gp = attn + ((size_t)bh * SS + i) * SS;
    float* rb = rows + w * SS;
    for (int it = 0; it < 64; ++it) rb[lane + it * 32] = gp[lane + it * 32];
    __syncthreads();
    float m = -1e30f;
    for (int it = 0; it < 64; ++it) {
        int j = lane + it * 32;
        int rel = j - i;
        bool ms = (rel >= -W2 && rel <= W2) || mk[j];
        if (ms) m = fmaxf(m, rb[j]);
    }
#pragma unroll
    for (int off = 16; off; off >>= 1) m = fmaxf(m, __shfl_xor_sync(0xffffffffu, m, off));
    float sum = 0.f;
    for (int it = 0; it < 64; ++it) {
        int j = lane + it * 32;
        int rel = j - i;
        bool ms = (rel >= -W2 && rel <= W2) || mk[j];
        if (ms) {
            float e = __expf(rb[j] - m);
            rb[j] = e;
            sum += e;
        }
    }
#pragma unroll
    for (int off = 16; off; off >>= 1) sum += __shfl_xor_sync(0xffffffffu, sum, off);
    float inv = 1.0f / sum;
    for (int it = 0; it < 64; ++it) {
        int j = lane + it * 32;
        int rel = j - i;
        bool ms = (rel >= -W2 && rel <= W2) || mk[j];
        gp[j] = ms ? rb[j] * inv : 0.f;
    }
}

// ---------------- K9: AV GEMM (pipelined, ldmatrix) ---------------------------
__global__ __launch_bounds__(256, 2) void av_mma(const float* __restrict__ attn) {
    __shared__ __nv_bfloat16 sAh[128 * SA], sAl[128 * SA];
    __shared__ __nv_bfloat16 sVh[2][64 * SA], sVl[2][64 * SA];
    int t = threadIdx.x, w = t >> 5, lane = t & 31;
    int wm = (w & 1) * 64, wn = (w >> 1) * 16;
    int g = lane >> 2, tg = lane & 3;
    int quad = lane >> 3, within = lane & 7;
    int bx = blockIdx.x, bh = blockIdx.y;
    const float* Ap = attn + ((size_t)bh * SS + bx * 128) * SS;
    const __nv_bfloat16* Vh = g_vthi + (size_t)bh * HD * SS;
    const __nv_bfloat16* Vl = g_vtlo + (size_t)bh * HD * SS;
    uint32_t sAh_u = s2u(sAh), sAl_u = s2u(sAl);
    uint32_t sVh_u[2] = {s2u(sVh[0]), s2u(sVh[1])};
    uint32_t sVl_u[2] = {s2u(sVl[0]), s2u(sVl[1])};
    int arow = (wm + within + (quad & 1) * 8) * SA + (quad >> 1) * 8;
    int brow = (wn + within + (quad >> 1) * 8) * SA + (quad & 1) * 8;

    float2 pv[8];
#pragma unroll
    for (int i = 0; i < 8; i++) {
        int lin = t + i * 256;
        int r = lin >> 4, h = lin & 15;
        pv[i] = *(const float2*)&Ap[(size_t)r * SS + h * 2];
    }
#pragma unroll
    for (int i = 0; i < 2; i++) {
        int lin = t + i * 256;
        int r = lin >> 3, h = lin & 7;
        cp8(&sVh[0][r * SA + h * 4], &Vh[(size_t)r * SS + h * 4]);
        cp8(&sVl[0][r * SA + h * 4], &Vl[(size_t)r * SS + h * 4]);
    }
    CP_COMMIT();

    float acc[4][2][4] = {};
    for (int ch = 0; ch < SS / 32; ++ch) {
        int buf = ch & 1;
        __syncthreads();
#pragma unroll
        for (int i = 0; i < 8; i++) {
            int lin = t + i * 256;
            int r = lin >> 4, h = lin & 15;
            uint32_t hi, lo;
            split2(pv[i].x, pv[i].y, hi, lo);
            *(uint32_t*)&sAh[r * SA + h * 2] = hi;
            *(uint32_t*)&sAl[r * SA + h * 2] = lo;
        }
        if (ch + 1 < SS / 32) {
            int k0n = (ch + 1) * 32;
#pragma unroll
            for (int i = 0; i < 2; i++) {
                int lin = t + i * 256;
                int r = lin >> 3, h = lin & 7;
                cp8(&sVh[buf ^ 1][r * SA + h * 4], &Vh[(size_t)r * SS + k0n + h * 4]);
                cp8(&sVl[buf ^ 1][r * SA + h * 4], &Vl[(size_t)r * SS + k0n + h * 4]);
            }
            CP_COMMIT();
#pragma unroll
            for (int i = 0; i < 8; i++) {
                int lin = t + i * 256;
                int r = lin >> 4, h = lin & 15;
                pv[i] = *(const float2*)&Ap[(size_t)r * SS + k0n + h * 2];
            }
            CP_WAIT1();
        } else {
            CP_WAIT0();
        }
        __syncthreads();
#pragma unroll
        for (int s = 0; s < 2; s++) {
            int kk = s * 16;
            uint32_t ah[4][4], al[4][4], bhf[4], blf[4];
#pragma unroll
            for (int mt = 0; mt < 4; mt++) {
                uint32_t off = (uint32_t)(arow + mt * 16 * SA + kk) * 2;
                ldsm_x4(ah[mt], sAh_u + off);
                ldsm_x4(al[mt], sAl_u + off);
            }
            {
                uint32_t off = (uint32_t)(brow + kk) * 2;
                ldsm_x4(bhf, sVh_u[buf] + off);
                ldsm_x4(blf, sVl_u[buf] + off);
            }
#pragma unroll
            for (int nt = 0; nt < 2; nt++) {
                const uint32_t* bhp = &bhf[nt * 2];
                const uint32_t* blp = &blf[nt * 2];
#pragma unroll
                for (int mt = 0; mt < 4; mt++) {
                    mma16816(acc[mt][nt], ah[mt], bhp);
                    mma16816(acc[mt][nt], ah[mt], blp);
                    mma16816(acc[mt][nt], al[mt], bhp);
                }
            }
        }
    }
    int b = bh >> 4, h = bh & 15;
#pragma unroll
    for (int mt = 0; mt < 4; mt++)
#pragma unroll
        for (int nt = 0; nt < 2; nt++) {
            float* c = acc[mt][nt];
#pragma unroll
            for (int half = 0; half < 2; half++) {
                int s = bx * 128 + wm + mt * 16 + g + half * 8;
                int d = wn + nt * 8 + tg * 2;
                size_t di = ((size_t)(b * SS + s)) * DD + h * 64 + d;
                uint32_t hi, lo;
                split2(c[half * 2], c[half * 2 + 1], hi, lo);
                *(uint32_t*)&g_ohi[di] = hi;
                *(uint32_t*)&g_olo[di] = lo;
            }
        }
}

// ---------------- K10: output projection --------------------------------------
__global__ __launch_bounds__(256, 2) void proj_mma(const float* __restrict__ bias,
                                                   float* __restrict__ out) {
    GEMM_PROLOG();
    int bx = blockIdx.x, by = blockIdx.y;
    gemm_db(g_ohi + (size_t)by * 128 * DD, g_olo + (size_t)by * 128 * DD, DD,
            g_w1hi + (size_t)bx * 128 * DD, g_w1lo + (size_t)bx * 128 * DD, DD,
            DD, dsm, t, wm, wn, lane, acc);
#pragma unroll
    for (int mt = 0; mt < 4; mt++)
#pragma unroll
        for (int nt = 0; nt < 4; nt++) {
            float* c = acc[mt][nt];
#pragma unroll
            for (int half = 0; half < 2; half++) {
                int m = by * 128 + wm + mt * 16 + g + half * 8;
                int n = bx * 128 + wn + nt * 8 + tg * 2;
                float2 o;
                o.x = c[half * 2] + bias[n];
                o.y = c[half * 2 + 1] + bias[n + 1];
                *(float2*)&out[(size_t)m * DD + n] = o;
            }
        }
}

// ---------------- launch ------------------------------------------------------
extern "C" void kernel_launch(void* const* d_in, const int* in_sizes, int n_in,
                              void* d_out, int out_size) {
    const float* x = (const float*)d_in[0];
    const float* qkv_w = (const float*)d_in[1];
    const float* qkv_b = (const float*)d_in[2];
    const float* out_w = (const float*)d_in[3];
    const float* out_b = (const float*)d_in[4];
    float* out = (float*)d_out;
    float* attn = out + (size_t)BB * SS * DD;

    const int SM_SMEM = 8 * SS * 4 + SS;
    cudaFuncSetAttribute(softmax_kernel, cudaFuncAttributeMaxDynamicSharedMemorySize, SM_SMEM);
    cudaFuncSetAttribute(qkv_mma, cudaFuncAttributeMaxDynamicSharedMemorySize, GEMM_DSMEM);
    cudaFuncSetAttribute(score_mma, cudaFuncAttributeMaxDynamicSharedMemorySize, SCORE_SMEM);
    cudaFuncSetAttribute(proj_mma, cudaFuncAttributeMaxDynamicSharedMemorySize, GEMM_DSMEM);
    cudaFuncSetAttribute(distkth_mma, cudaFuncAttributeMaxDynamicSharedMemorySize, DIST_SMEM);

    cvt_x<<<(BB * SS * DD + 255) / 256, 256>>>(x);
    cvt_w3<<<(3 * DD * DD + 255) / 256, 256>>>(qkv_w);
    cvt_w1<<<(DD * DD + 255) / 256, 256>>>(out_w);

    qkv_mma<<<dim3(24, 32), 256, GEMM_DSMEM>>>(qkv_b);
    stats_kernel<<<BH, 256>>>(x);
    distkth_mma<<<dim3(16, BH), 256, DIST_SMEM>>>();
    tls_kernel<<<BH, 256>>>();
    sort_mark_kernel<<<BH, 1024>>>();
    score_mma<<<dim3(16, 16, BH), 256, SCORE_SMEM>>>(attn);
    softmax_kernel<<<dim3(SS / 8, BH), 256, SM_SMEM>>>(attn);
    av_mma<<<dim3(16, BH), 256>>>(attn);
    proj_mma<<<dim3(8, 32), 256, GEMM_DSMEM>>>(out_b, out);
}